// round 1
// baseline (speedup 1.0000x reference)
#include <cuda_runtime.h>
#include <cuda_bf16.h>
#include <cstdint>
#include <cstdio>

#define BATCH 256
#define S2    32768
#define HID   512
#define HEADS 1024

// ---------------- scratch (device globals; no allocation allowed) ----------------
__device__ float g_cxpre[BATCH * HID];        // input @ W_c1^T + b_c1   [256,512]
__device__ float g_cx[BATCH];                 // context gate            [256]
__device__ float g_x1[BATCH * 2 * HID];       // [256,1024]
__device__ float g_x2[BATCH * HID];           // [256,512]
__device__ float g_x3[BATCH * HEADS];         // [256,1024]

// ---------------- bias / zero init ----------------
__global__ void bias_init_kernel(float* __restrict__ C, const float* __restrict__ bias,
                                 int total, int N) {
    int idx = blockIdx.x * blockDim.x + threadIdx.x;
    if (idx < total) {
        C[idx] = bias ? bias[idx % N] : 0.0f;
    }
}

// ---------------- split-K SGEMM:  C[m,n] += sum_k A[m,k] * W[n,k] ----------------
// A row-major [M,K], W row-major [N,K] (both K-contiguous), C row-major [M,N].
// C must be pre-initialized (bias or zero); partial sums accumulated with atomicAdd.
// Uses packed fma.rn.f32x2 (FFMA2) for full-rate fp32 on sm_103a.
#define BM 64
#define BN 64
#define BKK 32
#define AS_STRIDE 33   // [m][k], pad 1: conflict-free scalar access
#define WS_STRIDE 68   // [k][n], pad 4 (even): 8B-aligned float2 reads, conflict-free

__global__ __launch_bounds__(256) void splitk_gemm(
    const float* __restrict__ A, const float* __restrict__ W,
    float* __restrict__ C, int M, int N, int K, int kchunk)
{
    __shared__ float As[BM * AS_STRIDE];
    __shared__ float Ws[BKK * WS_STRIDE];

    const int tid  = threadIdx.x;
    const int mbase = blockIdx.y * BM;
    const int nbase = blockIdx.x * BN;
    const int k0    = blockIdx.z * kchunk;

    // warp-internal mapping: 8 n-groups x 4 m-groups (conflict-free smem reads)
    const int lane = tid & 31, warp = tid >> 5;
    const int wm = warp & 3, wn = warp >> 2;          // 4 m-warp-pos x 2 n-warp-pos
    const int m0 = wm * 16 + (lane >> 3) * 4;          // 0..60
    const int n0 = wn * 32 + (lane & 7) * 4;           // 0..60

    unsigned long long acc[4][2];
#pragma unroll
    for (int i = 0; i < 4; i++) { acc[i][0] = 0ull; acc[i][1] = 0ull; }

    for (int kk = k0; kk < k0 + kchunk; kk += BKK) {
        // cooperative tile loads: 2 float4 of A + 2 float4 of W per thread
#pragma unroll
        for (int l = 0; l < 2; l++) {
            int f   = tid + l * 256;          // 0..511
            int row = f >> 3;                 // 0..63
            int kc  = (f & 7) * 4;            // 0..28
            float4 va = *reinterpret_cast<const float4*>(
                &A[(size_t)(mbase + row) * K + kk + kc]);
            As[row * AS_STRIDE + kc + 0] = va.x;
            As[row * AS_STRIDE + kc + 1] = va.y;
            As[row * AS_STRIDE + kc + 2] = va.z;
            As[row * AS_STRIDE + kc + 3] = va.w;
            float4 vw = *reinterpret_cast<const float4*>(
                &W[(size_t)(nbase + row) * K + kk + kc]);
            Ws[(kc + 0) * WS_STRIDE + row] = vw.x;
            Ws[(kc + 1) * WS_STRIDE + row] = vw.y;
            Ws[(kc + 2) * WS_STRIDE + row] = vw.z;
            Ws[(kc + 3) * WS_STRIDE + row] = vw.w;
        }
        __syncthreads();

#pragma unroll
        for (int k = 0; k < BKK; k++) {
            unsigned long long pa[4];
#pragma unroll
            for (int i = 0; i < 4; i++) {
                unsigned int au = __float_as_uint(As[(m0 + i) * AS_STRIDE + k]);
                asm("mov.b64 %0, {%1, %1};" : "=l"(pa[i]) : "r"(au));
            }
            unsigned long long w0 = *reinterpret_cast<const unsigned long long*>(
                &Ws[k * WS_STRIDE + n0]);
            unsigned long long w1 = *reinterpret_cast<const unsigned long long*>(
                &Ws[k * WS_STRIDE + n0 + 2]);
#pragma unroll
            for (int i = 0; i < 4; i++) {
                asm("fma.rn.f32x2 %0, %1, %2, %0;" : "+l"(acc[i][0]) : "l"(pa[i]), "l"(w0));
                asm("fma.rn.f32x2 %0, %1, %2, %0;" : "+l"(acc[i][1]) : "l"(pa[i]), "l"(w1));
            }
        }
        __syncthreads();
    }

    // epilogue: atomic accumulation into pre-biased C
#pragma unroll
    for (int i = 0; i < 4; i++) {
#pragma unroll
        for (int j = 0; j < 2; j++) {
            float lo = __uint_as_float((unsigned)(acc[i][j] & 0xffffffffull));
            float hi = __uint_as_float((unsigned)(acc[i][j] >> 32));
            size_t base = (size_t)(mbase + m0 + i) * N + nbase + n0 + 2 * j;
            atomicAdd(&C[base], lo);
            atomicAdd(&C[base + 1], hi);
        }
    }
}

// ---------------- context gate: cx = sigmoid( tanh(cxpre_row) . W_c2 ) ----------------
__global__ void cx_kernel(const float* __restrict__ Wc2) {
    int row = blockIdx.x;
    int tid = threadIdx.x;  // 128
    float s = 0.f;
    for (int j = tid; j < HID; j += 128)
        s += tanhf(g_cxpre[row * HID + j]) * Wc2[j];
#pragma unroll
    for (int off = 16; off; off >>= 1) s += __shfl_xor_sync(0xffffffffu, s, off);
    __shared__ float red[4];
    if ((tid & 31) == 0) red[tid >> 5] = s;
    __syncthreads();
    if (tid == 0) {
        float t = red[0] + red[1] + red[2] + red[3];
        g_cx[row] = 1.0f / (1.0f + expf(-t));
    }
}

// ---------------- kWTA: keep the k = int(cx * N) largest entries of each row ----------
// Threshold via per-row bitonic sort (descending); ties broken by lowest index,
// matching the reference's stable argsort semantics.
template <int NWID>
__global__ void kwta_kernel(float* __restrict__ x) {
    __shared__ float s[NWID];
    __shared__ int cnt_gt;
    const int row = blockIdx.x;
    const int tid = threadIdx.x;  // 256
    float* xr = x + (size_t)row * NWID;

    for (int i = tid; i < NWID; i += 256) s[i] = xr[i];
    if (tid == 0) cnt_gt = 0;
    int k = (int)(g_cx[row] * (float)NWID);
    __syncthreads();

    if (k <= 0) {
        for (int i = tid; i < NWID; i += 256) xr[i] = 0.f;
        return;
    }
    if (k >= NWID) return;

    // bitonic sort, descending
    for (int size = 2; size <= NWID; size <<= 1) {
        for (int stride = size >> 1; stride > 0; stride >>= 1) {
            for (int i = tid; i < NWID / 2; i += 256) {
                int idx = ((i / stride) * stride) * 2 + (i % stride);
                int partner = idx + stride;
                bool up = (idx & size) != 0;
                float a = s[idx], b = s[partner];
                if ((a < b) != up) { s[idx] = b; s[partner] = a; }
            }
            __syncthreads();
        }
    }
    float T = s[k - 1];

    int local = 0;
    for (int i = tid; i < NWID; i += 256)
        if (xr[i] > T) local++;
    atomicAdd(&cnt_gt, local);
    __syncthreads();
    int r = k - cnt_gt;  // number of T-valued elements to keep (earliest indices)

    for (int i = tid; i < NWID; i += 256)
        if (xr[i] < T) xr[i] = 0.f;
    __syncthreads();

    if (tid == 0) {
        for (int i = 0; i < NWID; i++) {
            if (xr[i] == T) {
                if (r > 0) r--;
                else xr[i] = 0.f;
            }
        }
    }
}

// ---------------- launch ----------------
extern "C" void kernel_launch(void* const* d_in, const int* in_sizes, int n_in,
                              void* d_out, int out_size) {
    const float* input = (const float*)d_in[0];
    const float* W_c1  = (const float*)d_in[1];
    const float* b_c1  = (const float*)d_in[2];
    const float* W_c2  = (const float*)d_in[3];
    const float* W1    = (const float*)d_in[4];
    const float* b1    = (const float*)d_in[5];
    const float* W2    = (const float*)d_in[6];
    const float* b2    = (const float*)d_in[7];
    const float* W3    = (const float*)d_in[8];
    const float* b3    = (const float*)d_in[9];
    const float* W4    = (const float*)d_in[10];
    float* out = (float*)d_out;

    float *cxpre, *x1, *x2, *x3;
    cudaGetSymbolAddress((void**)&cxpre, g_cxpre);
    cudaGetSymbolAddress((void**)&x1, g_x1);
    cudaGetSymbolAddress((void**)&x2, g_x2);
    cudaGetSymbolAddress((void**)&x3, g_x3);

    // stage 0: init accumulators with biases (and zero the output for split-K)
    bias_init_kernel<<<(BATCH * HID + 255) / 256, 256>>>(cxpre, b_c1, BATCH * HID, HID);
    bias_init_kernel<<<(BATCH * 2 * HID + 255) / 256, 256>>>(x1, b1, BATCH * 2 * HID, 2 * HID);
    bias_init_kernel<<<(BATCH * HEADS + 255) / 256, 256>>>(out, nullptr, BATCH * HEADS, HEADS);

    // big GEMMs: input @ W_c1^T  and  input @ W1^T (split-K)
    {
        dim3 g(HID / BN, BATCH / BM, 16);          // kchunk = 2048
        splitk_gemm<<<g, 256>>>(input, W_c1, cxpre, BATCH, HID, S2, S2 / 16);
    }
    {
        dim3 g(2 * HID / BN, BATCH / BM, 8);       // kchunk = 4096
        splitk_gemm<<<g, 256>>>(input, W1, x1, BATCH, 2 * HID, S2, S2 / 8);
    }

    // context gate
    cx_kernel<<<BATCH, 128>>>(W_c2);

    // kWTA 1 (n=1024)
    kwta_kernel<2 * HID><<<BATCH, 256>>>(x1);

    // GEMM2: x1 @ W2^T + b2  -> [256,512], K=1024
    bias_init_kernel<<<(BATCH * HID + 255) / 256, 256>>>(x2, b2, BATCH * HID, HID);
    {
        dim3 g(HID / BN, BATCH / BM, 4);           // kchunk = 256
        splitk_gemm<<<g, 256>>>(x1, W2, x2, BATCH, HID, 2 * HID, (2 * HID) / 4);
    }
    kwta_kernel<HID><<<BATCH, 256>>>(x2);

    // GEMM3: x2 @ W3^T + b3  -> [256,1024], K=512
    bias_init_kernel<<<(BATCH * HEADS + 255) / 256, 256>>>(x3, b3, BATCH * HEADS, HEADS);
    {
        dim3 g(HEADS / BN, BATCH / BM, 2);         // kchunk = 256
        splitk_gemm<<<g, 256>>>(x2, W3, x3, BATCH, HEADS, HID, HID / 2);
    }
    kwta_kernel<HEADS><<<BATCH, 256>>>(x3);

    // GEMM4: x3 @ W4^T -> out [256,1024], K=1024 (out pre-zeroed)
    {
        dim3 g(HEADS / BN, BATCH / BM, 4);         // kchunk = 256
        splitk_gemm<<<g, 256>>>(x3, W4, out, BATCH, HEADS, HEADS, HEADS / 4);
    }
}

// round 2
// speedup vs baseline: 1.0037x; 1.0037x over previous
#include <cuda_runtime.h>
#include <cuda_bf16.h>
#include <cstdint>
#include <cstdio>

#define BATCH 256
#define S2    32768
#define HID   512
#define HEADS 1024

// ---------------- scratch (device globals; no allocation allowed) ----------------
__device__ float g_cxpre[BATCH * HID];        // input @ W_c1^T + b_c1   [256,512]
__device__ float g_cx[BATCH];                 // context gate            [256]
__device__ float g_x1[BATCH * 2 * HID];       // [256,1024]
__device__ float g_x2[BATCH * HID];           // [256,512]
__device__ float g_x3[BATCH * HEADS];         // [256,1024]

// ---------------- bias / zero init ----------------
__global__ void bias_init_kernel(float* __restrict__ C, const float* __restrict__ bias,
                                 int total, int N) {
    int idx = blockIdx.x * blockDim.x + threadIdx.x;
    if (idx < total) {
        C[idx] = bias ? bias[idx % N] : 0.0f;
    }
}

// ---------------- split-K SGEMM:  C[m,n] += sum_k A[m,k] * W[n,k] ----------------
// A row-major [M,K], W row-major [N,K] (both K-contiguous), C row-major [M,N].
// C must be pre-initialized (bias or zero); partial sums accumulated with atomicAdd.
// Uses packed fma.rn.f32x2 (FFMA2) for full-rate fp32 on sm_103a.
#define BM 64
#define BN 64
#define BKK 32
#define AS_STRIDE 33   // [m][k], pad 1: conflict-free scalar access
#define WS_STRIDE 68   // [k][n], pad 4 (even): 8B-aligned float2 reads, conflict-free

__global__ __launch_bounds__(256) void splitk_gemm(
    const float* __restrict__ A, const float* __restrict__ W,
    float* __restrict__ C, int M, int N, int K, int kchunk)
{
    __shared__ float As[BM * AS_STRIDE];
    __shared__ float Ws[BKK * WS_STRIDE];

    const int tid  = threadIdx.x;
    const int mbase = blockIdx.y * BM;
    const int nbase = blockIdx.x * BN;
    const int k0    = blockIdx.z * kchunk;

    // warp-internal mapping: 8 n-groups x 4 m-groups (conflict-free smem reads)
    const int lane = tid & 31, warp = tid >> 5;
    const int wm = warp & 3, wn = warp >> 2;          // 4 m-warp-pos x 2 n-warp-pos
    const int m0 = wm * 16 + (lane >> 3) * 4;          // 0..60
    const int n0 = wn * 32 + (lane & 7) * 4;           // 0..60

    unsigned long long acc[4][2];
#pragma unroll
    for (int i = 0; i < 4; i++) { acc[i][0] = 0ull; acc[i][1] = 0ull; }

    for (int kk = k0; kk < k0 + kchunk; kk += BKK) {
        // cooperative tile loads: 2 float4 of A + 2 float4 of W per thread
#pragma unroll
        for (int l = 0; l < 2; l++) {
            int f   = tid + l * 256;          // 0..511
            int row = f >> 3;                 // 0..63
            int kc  = (f & 7) * 4;            // 0..28
            float4 va = *reinterpret_cast<const float4*>(
                &A[(size_t)(mbase + row) * K + kk + kc]);
            As[row * AS_STRIDE + kc + 0] = va.x;
            As[row * AS_STRIDE + kc + 1] = va.y;
            As[row * AS_STRIDE + kc + 2] = va.z;
            As[row * AS_STRIDE + kc + 3] = va.w;
            float4 vw = *reinterpret_cast<const float4*>(
                &W[(size_t)(nbase + row) * K + kk + kc]);
            Ws[(kc + 0) * WS_STRIDE + row] = vw.x;
            Ws[(kc + 1) * WS_STRIDE + row] = vw.y;
            Ws[(kc + 2) * WS_STRIDE + row] = vw.z;
            Ws[(kc + 3) * WS_STRIDE + row] = vw.w;
        }
        __syncthreads();

#pragma unroll
        for (int k = 0; k < BKK; k++) {
            unsigned long long pa[4];
#pragma unroll
            for (int i = 0; i < 4; i++) {
                unsigned int au = __float_as_uint(As[(m0 + i) * AS_STRIDE + k]);
                asm("mov.b64 %0, {%1, %1};" : "=l"(pa[i]) : "r"(au));
            }
            unsigned long long w0 = *reinterpret_cast<const unsigned long long*>(
                &Ws[k * WS_STRIDE + n0]);
            unsigned long long w1 = *reinterpret_cast<const unsigned long long*>(
                &Ws[k * WS_STRIDE + n0 + 2]);
#pragma unroll
            for (int i = 0; i < 4; i++) {
                asm("fma.rn.f32x2 %0, %1, %2, %0;" : "+l"(acc[i][0]) : "l"(pa[i]), "l"(w0));
                asm("fma.rn.f32x2 %0, %1, %2, %0;" : "+l"(acc[i][1]) : "l"(pa[i]), "l"(w1));
            }
        }
        __syncthreads();
    }

    // epilogue: atomic accumulation into pre-biased C
#pragma unroll
    for (int i = 0; i < 4; i++) {
#pragma unroll
        for (int j = 0; j < 2; j++) {
            float lo = __uint_as_float((unsigned)(acc[i][j] & 0xffffffffull));
            float hi = __uint_as_float((unsigned)(acc[i][j] >> 32));
            size_t base = (size_t)(mbase + m0 + i) * N + nbase + n0 + 2 * j;
            atomicAdd(&C[base], lo);
            atomicAdd(&C[base + 1], hi);
        }
    }
}

// ---------------- context gate: cx = sigmoid( tanh(cxpre_row) . W_c2 ) ----------------
__global__ void cx_kernel(const float* __restrict__ Wc2) {
    int row = blockIdx.x;
    int tid = threadIdx.x;  // 128
    float s = 0.f;
    for (int j = tid; j < HID; j += 128)
        s += tanhf(g_cxpre[row * HID + j]) * Wc2[j];
#pragma unroll
    for (int off = 16; off; off >>= 1) s += __shfl_xor_sync(0xffffffffu, s, off);
    __shared__ float red[4];
    if ((tid & 31) == 0) red[tid >> 5] = s;
    __syncthreads();
    if (tid == 0) {
        float t = red[0] + red[1] + red[2] + red[3];
        g_cx[row] = 1.0f / (1.0f + expf(-t));
    }
}

// ---------------- kWTA: keep the k = int(cx * N) largest entries of each row ----------
// Threshold via per-row bitonic sort (descending); ties broken by lowest index,
// matching the reference's stable argsort semantics.
template <int NWID>
__global__ void kwta_kernel(float* __restrict__ x) {
    __shared__ float s[NWID];
    __shared__ int cnt_gt;
    const int row = blockIdx.x;
    const int tid = threadIdx.x;  // 256
    float* xr = x + (size_t)row * NWID;

    for (int i = tid; i < NWID; i += 256) s[i] = xr[i];
    if (tid == 0) cnt_gt = 0;
    int k = (int)(g_cx[row] * (float)NWID);
    __syncthreads();

    if (k <= 0) {
        for (int i = tid; i < NWID; i += 256) xr[i] = 0.f;
        return;
    }
    if (k >= NWID) return;

    // bitonic sort, descending
    for (int size = 2; size <= NWID; size <<= 1) {
        for (int stride = size >> 1; stride > 0; stride >>= 1) {
            for (int i = tid; i < NWID / 2; i += 256) {
                int idx = ((i / stride) * stride) * 2 + (i % stride);
                int partner = idx + stride;
                bool up = (idx & size) != 0;
                float a = s[idx], b = s[partner];
                if ((a < b) != up) { s[idx] = b; s[partner] = a; }
            }
            __syncthreads();
        }
    }
    float T = s[k - 1];

    int local = 0;
    for (int i = tid; i < NWID; i += 256)
        if (xr[i] > T) local++;
    atomicAdd(&cnt_gt, local);
    __syncthreads();
    int r = k - cnt_gt;  // number of T-valued elements to keep (earliest indices)

    for (int i = tid; i < NWID; i += 256)
        if (xr[i] < T) xr[i] = 0.f;
    __syncthreads();

    if (tid == 0) {
        for (int i = 0; i < NWID; i++) {
            if (xr[i] == T) {
                if (r > 0) r--;
                else xr[i] = 0.f;
            }
        }
    }
}

// ---------------- launch ----------------
extern "C" void kernel_launch(void* const* d_in, const int* in_sizes, int n_in,
                              void* d_out, int out_size) {
    const float* input = (const float*)d_in[0];
    const float* W_c1  = (const float*)d_in[1];
    const float* b_c1  = (const float*)d_in[2];
    const float* W_c2  = (const float*)d_in[3];
    const float* W1    = (const float*)d_in[4];
    const float* b1    = (const float*)d_in[5];
    const float* W2    = (const float*)d_in[6];
    const float* b2    = (const float*)d_in[7];
    const float* W3    = (const float*)d_in[8];
    const float* b3    = (const float*)d_in[9];
    const float* W4    = (const float*)d_in[10];
    float* out = (float*)d_out;

    float *cxpre, *x1, *x2, *x3;
    cudaGetSymbolAddress((void**)&cxpre, g_cxpre);
    cudaGetSymbolAddress((void**)&x1, g_x1);
    cudaGetSymbolAddress((void**)&x2, g_x2);
    cudaGetSymbolAddress((void**)&x3, g_x3);

    // stage 0: init accumulators with biases (and zero the output for split-K)
    bias_init_kernel<<<(BATCH * HID + 255) / 256, 256>>>(cxpre, b_c1, BATCH * HID, HID);
    bias_init_kernel<<<(BATCH * 2 * HID + 255) / 256, 256>>>(x1, b1, BATCH * 2 * HID, 2 * HID);
    bias_init_kernel<<<(BATCH * HEADS + 255) / 256, 256>>>(out, nullptr, BATCH * HEADS, HEADS);

    // big GEMMs: input @ W_c1^T  and  input @ W1^T (split-K)
    {
        dim3 g(HID / BN, BATCH / BM, 16);          // kchunk = 2048
        splitk_gemm<<<g, 256>>>(input, W_c1, cxpre, BATCH, HID, S2, S2 / 16);
    }
    {
        dim3 g(2 * HID / BN, BATCH / BM, 8);       // kchunk = 4096
        splitk_gemm<<<g, 256>>>(input, W1, x1, BATCH, 2 * HID, S2, S2 / 8);
    }

    // context gate
    cx_kernel<<<BATCH, 128>>>(W_c2);

    // kWTA 1 (n=1024)
    kwta_kernel<2 * HID><<<BATCH, 256>>>(x1);

    // GEMM2: x1 @ W2^T + b2  -> [256,512], K=1024
    bias_init_kernel<<<(BATCH * HID + 255) / 256, 256>>>(x2, b2, BATCH * HID, HID);
    {
        dim3 g(HID / BN, BATCH / BM, 4);           // kchunk = 256
        splitk_gemm<<<g, 256>>>(x1, W2, x2, BATCH, HID, 2 * HID, (2 * HID) / 4);
    }
    kwta_kernel<HID><<<BATCH, 256>>>(x2);

    // GEMM3: x2 @ W3^T + b3  -> [256,1024], K=512
    bias_init_kernel<<<(BATCH * HEADS + 255) / 256, 256>>>(x3, b3, BATCH * HEADS, HEADS);
    {
        dim3 g(HEADS / BN, BATCH / BM, 2);         // kchunk = 256
        splitk_gemm<<<g, 256>>>(x2, W3, x3, BATCH, HEADS, HID, HID / 2);
    }
    kwta_kernel<HEADS><<<BATCH, 256>>>(x3);

    // GEMM4: x3 @ W4^T -> out [256,1024], K=1024 (out pre-zeroed)
    {
        dim3 g(HEADS / BN, BATCH / BM, 4);         // kchunk = 256
        splitk_gemm<<<g, 256>>>(x3, W4, out, BATCH, HEADS, HEADS, HEADS / 4);
    }
}

// round 4
// speedup vs baseline: 2.7919x; 2.7815x over previous
#include <cuda_runtime.h>
#include <cuda_fp16.h>
#include <cstdint>

#define BATCH 256
#define S2    32768
#define HID   512
#define HEADS 1024

// ---------------- scratch ----------------
__device__ float g_cxpre[BATCH * HID];
__device__ float g_cx[BATCH];
__device__ float g_x1[BATCH * 2 * HID];
__device__ float g_x2[BATCH * HID];
__device__ float g_x3[BATCH * HEADS];

// ---------------- bias / zero init ----------------
__global__ void bias_init_kernel(float* __restrict__ C, const float* __restrict__ bias,
                                 int total, int N) {
    int idx = blockIdx.x * blockDim.x + threadIdx.x;
    if (idx < total) C[idx] = bias ? bias[idx % N] : 0.0f;
}

// ---------------- fp32 split-K GEMM (small layers) ----------------
#define BM 64
#define BN 64
#define BKK 32
#define AS_STRIDE 33
#define WS_STRIDE 68

__global__ __launch_bounds__(256) void splitk_gemm(
    const float* __restrict__ A, const float* __restrict__ W,
    float* __restrict__ C, int M, int N, int K, int kchunk)
{
    __shared__ float As[BM * AS_STRIDE];
    __shared__ float Ws[BKK * WS_STRIDE];

    const int tid  = threadIdx.x;
    const int mbase = blockIdx.y * BM;
    const int nbase = blockIdx.x * BN;
    const int k0    = blockIdx.z * kchunk;

    const int lane = tid & 31, warp = tid >> 5;
    const int wm = warp & 3, wn = warp >> 2;
    const int m0 = wm * 16 + (lane >> 3) * 4;
    const int n0 = wn * 32 + (lane & 7) * 4;

    unsigned long long acc[4][2];
#pragma unroll
    for (int i = 0; i < 4; i++) { acc[i][0] = 0ull; acc[i][1] = 0ull; }

    for (int kk = k0; kk < k0 + kchunk; kk += BKK) {
#pragma unroll
        for (int l = 0; l < 2; l++) {
            int f   = tid + l * 256;
            int row = f >> 3;
            int kc  = (f & 7) * 4;
            float4 va = *reinterpret_cast<const float4*>(&A[(size_t)(mbase + row) * K + kk + kc]);
            As[row * AS_STRIDE + kc + 0] = va.x;
            As[row * AS_STRIDE + kc + 1] = va.y;
            As[row * AS_STRIDE + kc + 2] = va.z;
            As[row * AS_STRIDE + kc + 3] = va.w;
            float4 vw = *reinterpret_cast<const float4*>(&W[(size_t)(nbase + row) * K + kk + kc]);
            Ws[(kc + 0) * WS_STRIDE + row] = vw.x;
            Ws[(kc + 1) * WS_STRIDE + row] = vw.y;
            Ws[(kc + 2) * WS_STRIDE + row] = vw.z;
            Ws[(kc + 3) * WS_STRIDE + row] = vw.w;
        }
        __syncthreads();

#pragma unroll
        for (int k = 0; k < BKK; k++) {
            unsigned long long pa[4];
#pragma unroll
            for (int i = 0; i < 4; i++) {
                unsigned int au = __float_as_uint(As[(m0 + i) * AS_STRIDE + k]);
                asm("mov.b64 %0, {%1, %1};" : "=l"(pa[i]) : "r"(au));
            }
            unsigned long long w0 = *reinterpret_cast<const unsigned long long*>(&Ws[k * WS_STRIDE + n0]);
            unsigned long long w1 = *reinterpret_cast<const unsigned long long*>(&Ws[k * WS_STRIDE + n0 + 2]);
#pragma unroll
            for (int i = 0; i < 4; i++) {
                asm("fma.rn.f32x2 %0, %1, %2, %0;" : "+l"(acc[i][0]) : "l"(pa[i]), "l"(w0));
                asm("fma.rn.f32x2 %0, %1, %2, %0;" : "+l"(acc[i][1]) : "l"(pa[i]), "l"(w1));
            }
        }
        __syncthreads();
    }

#pragma unroll
    for (int i = 0; i < 4; i++) {
#pragma unroll
        for (int j = 0; j < 2; j++) {
            float lo = __uint_as_float((unsigned)(acc[i][j] & 0xffffffffull));
            float hi = __uint_as_float((unsigned)(acc[i][j] >> 32));
            size_t base = (size_t)(mbase + m0 + i) * N + nbase + n0 + 2 * j;
            atomicAdd(&C[base], lo);
            atomicAdd(&C[base + 1], hi);
        }
    }
}

// ============================================================================
// Big GEMMs (K=32768) via mma.sync fp16 hi/lo 3-product (fp32-class accuracy).
// A scaled x256, W scaled x4096; epilogue rescales by 2^-20.
// CTA: 128x128 output tile. Grid: 24 tiles x splitK(6) = 144 CTAs.
// ============================================================================
#define GB_STRIDE 80          // padded smem row (32 fp16 = 64B + 16B pad) -> ldmatrix conflict-free
#define GB_TILE   (128 * GB_STRIDE)   // 10240
#define GB_BUF    (4 * GB_TILE)       // A_hi, A_lo, W_hi, W_lo = 40960
#define GB_SMEM   (2 * GB_BUF)        // 81920
#define SCALE_A 256.0f
#define SCALE_W 4096.0f
#define INV_SCALE (1.0f / (256.0f * 4096.0f))

__device__ __forceinline__ uint32_t smem_u32(const void* p) {
    uint32_t a;
    asm("{ .reg .u64 t; cvta.to.shared.u64 t, %1; cvt.u32.u64 %0, t; }" : "=r"(a) : "l"(p));
    return a;
}
__device__ __forceinline__ void ldsm_x4(uint32_t& r0, uint32_t& r1, uint32_t& r2,
                                        uint32_t& r3, uint32_t addr) {
    asm volatile("ldmatrix.sync.aligned.m8n8.x4.shared.b16 {%0,%1,%2,%3}, [%4];"
                 : "=r"(r0), "=r"(r1), "=r"(r2), "=r"(r3) : "r"(addr));
}
__device__ __forceinline__ void mma_f16(float* d, const uint32_t* a, const uint32_t* b) {
    asm volatile("mma.sync.aligned.m16n8k16.row.col.f32.f16.f16.f32 "
                 "{%0,%1,%2,%3}, {%4,%5,%6,%7}, {%8,%9}, {%0,%1,%2,%3};"
                 : "+f"(d[0]), "+f"(d[1]), "+f"(d[2]), "+f"(d[3])
                 : "r"(a[0]), "r"(a[1]), "r"(a[2]), "r"(a[3]), "r"(b[0]), "r"(b[1]));
}
__device__ __forceinline__ void split4h(float4 v, float sc,
                                        uint32_t& h0, uint32_t& h1,
                                        uint32_t& l0, uint32_t& l1) {
    float x = v.x * sc, y = v.y * sc, z = v.z * sc, w = v.w * sc;
    __half2 a01 = __floats2half2_rn(x, y);
    __half2 a23 = __floats2half2_rn(z, w);
    float2 f01 = __half22float2(a01);
    float2 f23 = __half22float2(a23);
    __half2 r01 = __floats2half2_rn(x - f01.x, y - f01.y);
    __half2 r23 = __floats2half2_rn(z - f23.x, w - f23.y);
    h0 = *reinterpret_cast<uint32_t*>(&a01);
    h1 = *reinterpret_cast<uint32_t*>(&a23);
    l0 = *reinterpret_cast<uint32_t*>(&r01);
    l1 = *reinterpret_cast<uint32_t*>(&r23);
}

__global__ __launch_bounds__(256, 1) void big_gemm_hmma(
    const float* __restrict__ A,
    const float* __restrict__ Wc1, const float* __restrict__ W1)
{
    extern __shared__ char smem[];
    const uint32_t sbase = smem_u32(smem);
    const int tid = threadIdx.x;
    const int lane = tid & 31, wid = tid >> 5;
    const int wm = wid & 3, wn = wid >> 2;

    // job decode: 24 tiles x 6 split-K
    int b = blockIdx.x;
    int t = b / 6, z = b % 6;
    const float* W; float* C; int N, mt, nt;
    if (t < 8) { W = Wc1; C = g_cxpre; N = HID;     mt = t & 1; nt = t >> 1; }
    else { t -= 8; W = W1; C = g_x1;   N = 2 * HID; mt = t & 1; nt = t >> 1; }
    const int mbase = mt * 128, nbase = nt * 128;
    const int c0 = z * 1024 / 6, c1 = (z + 1) * 1024 / 6;   // chunks of K=32

    // loader mapping: 256 threads -> 32 rows x 8 float4-groups, 4 row-blocks
    const int lrow = tid >> 3;
    const int lg   = tid & 7;
    const float* aB = A + (size_t)(mbase + lrow) * S2 + lg * 4;
    const float* wB = W + (size_t)(nbase + lrow) * S2 + lg * 4;

    float acc[2][8][4];
#pragma unroll
    for (int i = 0; i < 2; i++)
#pragma unroll
        for (int j = 0; j < 8; j++)
#pragma unroll
            for (int r = 0; r < 4; r++) acc[i][j][r] = 0.f;

    float4 Ar[4], Wr[4];
    {
        size_t kf = (size_t)c0 * 32;
#pragma unroll
        for (int i = 0; i < 4; i++) {
            Ar[i] = *reinterpret_cast<const float4*>(aB + (size_t)(32 * i) * S2 + kf);
            Wr[i] = *reinterpret_cast<const float4*>(wB + (size_t)(32 * i) * S2 + kf);
        }
    }

    for (int ci = c0; ci < c1; ci++) {
        const int p = ci & 1;
        char* buf = smem + p * GB_BUF;
        // convert + store staged chunk
#pragma unroll
        for (int i = 0; i < 4; i++) {
            uint32_t h0, h1, l0, l1;
            uint32_t off = (uint32_t)(lrow + 32 * i) * GB_STRIDE + lg * 8;
            split4h(Ar[i], SCALE_A, h0, h1, l0, l1);
            *reinterpret_cast<uint2*>(buf + 0 * GB_TILE + off) = make_uint2(h0, h1);
            *reinterpret_cast<uint2*>(buf + 1 * GB_TILE + off) = make_uint2(l0, l1);
            split4h(Wr[i], SCALE_W, h0, h1, l0, l1);
            *reinterpret_cast<uint2*>(buf + 2 * GB_TILE + off) = make_uint2(h0, h1);
            *reinterpret_cast<uint2*>(buf + 3 * GB_TILE + off) = make_uint2(l0, l1);
        }
        __syncthreads();
        if (ci + 1 < c1) {
            size_t kf = (size_t)(ci + 1) * 32;
#pragma unroll
            for (int i = 0; i < 4; i++) {
                Ar[i] = *reinterpret_cast<const float4*>(aB + (size_t)(32 * i) * S2 + kf);
                Wr[i] = *reinterpret_cast<const float4*>(wB + (size_t)(32 * i) * S2 + kf);
            }
        }
        // MMA on current buffer
        const uint32_t bufb = sbase + p * GB_BUF;
        const uint32_t a_base = bufb + (uint32_t)(wm * 32 + (lane & 15)) * GB_STRIDE
                              + (lane >> 4) * 16;
        const uint32_t b_base = bufb + 2 * GB_TILE
                              + (uint32_t)(wn * 64 + (lane & 7) + ((lane >> 4) << 3)) * GB_STRIDE
                              + ((lane >> 3) & 1) * 16;
#pragma unroll
        for (int ks = 0; ks < 2; ks++) {
            uint32_t af[2][2][4];
            uint32_t bf[2][8][2];
#pragma unroll
            for (int s = 0; s < 2; s++)
#pragma unroll
                for (int mi = 0; mi < 2; mi++)
                    ldsm_x4(af[s][mi][0], af[s][mi][1], af[s][mi][2], af[s][mi][3],
                            a_base + s * GB_TILE + mi * (16 * GB_STRIDE) + ks * 32);
#pragma unroll
            for (int s = 0; s < 2; s++)
#pragma unroll
                for (int nj2 = 0; nj2 < 4; nj2++) {
                    uint32_t r0, r1, r2, r3;
                    ldsm_x4(r0, r1, r2, r3,
                            b_base + s * GB_TILE + nj2 * (16 * GB_STRIDE) + ks * 32);
                    bf[s][nj2 * 2][0] = r0; bf[s][nj2 * 2][1] = r1;
                    bf[s][nj2 * 2 + 1][0] = r2; bf[s][nj2 * 2 + 1][1] = r3;
                }
#pragma unroll
            for (int mi = 0; mi < 2; mi++)
#pragma unroll
                for (int nj = 0; nj < 8; nj++) {
                    mma_f16(acc[mi][nj], af[0][mi], bf[0][nj]);   // hi*hi
                    mma_f16(acc[mi][nj], af[0][mi], bf[1][nj]);   // hi*lo
                    mma_f16(acc[mi][nj], af[1][mi], bf[0][nj]);   // lo*hi
                }
        }
        __syncthreads();
    }

    // epilogue: rescale + atomic accumulate into bias-preinit C
#pragma unroll
    for (int mi = 0; mi < 2; mi++) {
        int row0 = mbase + wm * 32 + mi * 16 + (lane >> 2);
#pragma unroll
        for (int nj = 0; nj < 8; nj++) {
            int col = nbase + wn * 64 + nj * 8 + (lane & 3) * 2;
            float* Cp = C + (size_t)row0 * N + col;
            atomicAdd(Cp,             acc[mi][nj][0] * INV_SCALE);
            atomicAdd(Cp + 1,         acc[mi][nj][1] * INV_SCALE);
            atomicAdd(Cp + 8 * N,     acc[mi][nj][2] * INV_SCALE);
            atomicAdd(Cp + 8 * N + 1, acc[mi][nj][3] * INV_SCALE);
        }
    }
}

// ---------------- context gate ----------------
__global__ void cx_kernel(const float* __restrict__ Wc2) {
    int row = blockIdx.x;
    int tid = threadIdx.x;
    float s = 0.f;
    for (int j = tid; j < HID; j += 128)
        s += tanhf(g_cxpre[row * HID + j]) * Wc2[j];
#pragma unroll
    for (int off = 16; off; off >>= 1) s += __shfl_xor_sync(0xffffffffu, s, off);
    __shared__ float red[4];
    if ((tid & 31) == 0) red[tid >> 5] = s;
    __syncthreads();
    if (tid == 0) {
        float t = red[0] + red[1] + red[2] + red[3];
        g_cx[row] = 1.0f / (1.0f + expf(-t));
    }
}

// ---------------- kWTA ----------------
template <int NWID>
__global__ void kwta_kernel(float* __restrict__ x) {
    __shared__ float s[NWID];
    __shared__ int cnt_gt, cnt_eq;
    const int row = blockIdx.x;
    const int tid = threadIdx.x;
    float* xr = x + (size_t)row * NWID;

    for (int i = tid; i < NWID; i += 256) s[i] = xr[i];
    if (tid == 0) { cnt_gt = 0; cnt_eq = 0; }
    int k = (int)(g_cx[row] * (float)NWID);
    __syncthreads();

    if (k <= 0) {
        for (int i = tid; i < NWID; i += 256) xr[i] = 0.f;
        return;
    }
    if (k >= NWID) return;

    for (int size = 2; size <= NWID; size <<= 1) {
        for (int stride = size >> 1; stride > 0; stride >>= 1) {
            for (int i = tid; i < NWID / 2; i += 256) {
                int idx = ((i / stride) * stride) * 2 + (i % stride);
                int partner = idx + stride;
                bool up = (idx & size) != 0;
                float a = s[idx], b2 = s[partner];
                if ((a < b2) != up) { s[idx] = b2; s[partner] = a; }
            }
            __syncthreads();
        }
    }
    float T = s[k - 1];

    int lg_ = 0, le_ = 0;
    for (int i = tid; i < NWID; i += 256) {
        float v = xr[i];
        if (v > T) lg_++;
        else if (v == T) le_++;
    }
    atomicAdd(&cnt_gt, lg_);
    atomicAdd(&cnt_eq, le_);
    __syncthreads();
    int r = k - cnt_gt;

    for (int i = tid; i < NWID; i += 256)
        if (xr[i] < T) xr[i] = 0.f;
    __syncthreads();

    if (cnt_eq != r) {     // rare tie-surplus path
        if (tid == 0) {
            int rr = r;
            for (int i = 0; i < NWID; i++) {
                if (xr[i] == T) {
                    if (rr > 0) rr--;
                    else xr[i] = 0.f;
                }
            }
        }
    }
}

// ---------------- launch ----------------
extern "C" void kernel_launch(void* const* d_in, const int* in_sizes, int n_in,
                              void* d_out, int out_size) {
    const float* input = (const float*)d_in[0];
    const float* W_c1  = (const float*)d_in[1];
    const float* b_c1  = (const float*)d_in[2];
    const float* W_c2  = (const float*)d_in[3];
    const float* W1    = (const float*)d_in[4];
    const float* b1    = (const float*)d_in[5];
    const float* W2    = (const float*)d_in[6];
    const float* b2    = (const float*)d_in[7];
    const float* W3    = (const float*)d_in[8];
    const float* b3    = (const float*)d_in[9];
    const float* W4    = (const float*)d_in[10];
    float* out = (float*)d_out;

    float *cxpre, *x1, *x2, *x3;
    cudaGetSymbolAddress((void**)&cxpre, g_cxpre);
    cudaGetSymbolAddress((void**)&x1, g_x1);
    cudaGetSymbolAddress((void**)&x2, g_x2);
    cudaGetSymbolAddress((void**)&x3, g_x3);

    cudaFuncSetAttribute(big_gemm_hmma, cudaFuncAttributeMaxDynamicSharedMemorySize, GB_SMEM);

    bias_init_kernel<<<(BATCH * HID + 255) / 256, 256>>>(cxpre, b_c1, BATCH * HID, HID);
    bias_init_kernel<<<(BATCH * 2 * HID + 255) / 256, 256>>>(x1, b1, BATCH * 2 * HID, 2 * HID);
    bias_init_kernel<<<(BATCH * HEADS + 255) / 256, 256>>>(out, nullptr, BATCH * HEADS, HEADS);

    // both big GEMMs in one HMMA launch (144 CTAs)
    big_gemm_hmma<<<144, 256, GB_SMEM>>>(input, W_c1, W1);

    cx_kernel<<<BATCH, 128>>>(W_c2);
    kwta_kernel<2 * HID><<<BATCH, 256>>>(x1);

    bias_init_kernel<<<(BATCH * HID + 255) / 256, 256>>>(x2, b2, BATCH * HID, HID);
    {
        dim3 g(HID / BN, BATCH / BM, 4);
        splitk_gemm<<<g, 256>>>(x1, W2, x2, BATCH, HID, 2 * HID, (2 * HID) / 4);
    }
    kwta_kernel<HID><<<BATCH, 256>>>(x2);

    bias_init_kernel<<<(BATCH * HEADS + 255) / 256, 256>>>(x3, b3, BATCH * HEADS, HEADS);
    {
        dim3 g(HEADS / BN, BATCH / BM, 2);
        splitk_gemm<<<g, 256>>>(x2, W3, x3, BATCH, HEADS, HID, HID / 2);
    }
    kwta_kernel<HEADS><<<BATCH, 256>>>(x3);

    {
        dim3 g(HEADS / BN, BATCH / BM, 4);
        splitk_gemm<<<g, 256>>>(x3, W4, out, BATCH, HEADS, HEADS, HEADS / 4);
    }
}

// round 5
// speedup vs baseline: 3.0960x; 1.1089x over previous
#include <cuda_runtime.h>
#include <cuda_fp16.h>
#include <cstdint>

#define BATCH 256
#define S2    32768
#define HID   512
#define HEADS 1024

// ---------------- scratch ----------------
__device__ float g_cxpre[BATCH * HID];
__device__ float g_cx[BATCH];
__device__ float g_x1[BATCH * 2 * HID];
__device__ float g_x2[BATCH * HID];
__device__ float g_x3[BATCH * HEADS];

// ---------------- bias / zero init ----------------
__global__ void bias_init_kernel(float* __restrict__ C, const float* __restrict__ bias,
                                 int total, int N) {
    int idx = blockIdx.x * blockDim.x + threadIdx.x;
    if (idx < total) C[idx] = bias ? bias[idx % N] : 0.0f;
}

// ---------------- fp32 split-K GEMM (small layers) ----------------
#define BM 64
#define BN 64
#define BKK 32
#define AS_STRIDE 33
#define WS_STRIDE 68

__global__ __launch_bounds__(256) void splitk_gemm(
    const float* __restrict__ A, const float* __restrict__ W,
    float* __restrict__ C, int M, int N, int K, int kchunk)
{
    __shared__ float As[BM * AS_STRIDE];
    __shared__ float Ws[BKK * WS_STRIDE];

    const int tid  = threadIdx.x;
    const int mbase = blockIdx.y * BM;
    const int nbase = blockIdx.x * BN;
    const int k0    = blockIdx.z * kchunk;

    const int lane = tid & 31, warp = tid >> 5;
    const int wm = warp & 3, wn = warp >> 2;
    const int m0 = wm * 16 + (lane >> 3) * 4;
    const int n0 = wn * 32 + (lane & 7) * 4;

    unsigned long long acc[4][2];
#pragma unroll
    for (int i = 0; i < 4; i++) { acc[i][0] = 0ull; acc[i][1] = 0ull; }

    for (int kk = k0; kk < k0 + kchunk; kk += BKK) {
#pragma unroll
        for (int l = 0; l < 2; l++) {
            int f   = tid + l * 256;
            int row = f >> 3;
            int kc  = (f & 7) * 4;
            float4 va = *reinterpret_cast<const float4*>(&A[(size_t)(mbase + row) * K + kk + kc]);
            As[row * AS_STRIDE + kc + 0] = va.x;
            As[row * AS_STRIDE + kc + 1] = va.y;
            As[row * AS_STRIDE + kc + 2] = va.z;
            As[row * AS_STRIDE + kc + 3] = va.w;
            float4 vw = *reinterpret_cast<const float4*>(&W[(size_t)(nbase + row) * K + kk + kc]);
            Ws[(kc + 0) * WS_STRIDE + row] = vw.x;
            Ws[(kc + 1) * WS_STRIDE + row] = vw.y;
            Ws[(kc + 2) * WS_STRIDE + row] = vw.z;
            Ws[(kc + 3) * WS_STRIDE + row] = vw.w;
        }
        __syncthreads();

#pragma unroll
        for (int k = 0; k < BKK; k++) {
            unsigned long long pa[4];
#pragma unroll
            for (int i = 0; i < 4; i++) {
                unsigned int au = __float_as_uint(As[(m0 + i) * AS_STRIDE + k]);
                asm("mov.b64 %0, {%1, %1};" : "=l"(pa[i]) : "r"(au));
            }
            unsigned long long w0 = *reinterpret_cast<const unsigned long long*>(&Ws[k * WS_STRIDE + n0]);
            unsigned long long w1 = *reinterpret_cast<const unsigned long long*>(&Ws[k * WS_STRIDE + n0 + 2]);
#pragma unroll
            for (int i = 0; i < 4; i++) {
                asm("fma.rn.f32x2 %0, %1, %2, %0;" : "+l"(acc[i][0]) : "l"(pa[i]), "l"(w0));
                asm("fma.rn.f32x2 %0, %1, %2, %0;" : "+l"(acc[i][1]) : "l"(pa[i]), "l"(w1));
            }
        }
        __syncthreads();
    }

#pragma unroll
    for (int i = 0; i < 4; i++) {
#pragma unroll
        for (int j = 0; j < 2; j++) {
            float lo = __uint_as_float((unsigned)(acc[i][j] & 0xffffffffull));
            float hi = __uint_as_float((unsigned)(acc[i][j] >> 32));
            size_t base = (size_t)(mbase + m0 + i) * N + nbase + n0 + 2 * j;
            atomicAdd(&C[base], lo);
            atomicAdd(&C[base + 1], hi);
        }
    }
}

// ============================================================================
// Big GEMMs (K=32768) via mma.sync fp16 hi/lo 3-product.
// NUMERICS FROZEN vs round-4 kernel (same values, same MMA order, same split-K,
// same epilogue). Only the buffering changed: 3-stage smem pipeline with one
// __syncthreads per iteration so convert+STS overlaps MMA across warps.
// ============================================================================
#define GB_STRIDE 80
#define GB_TILE   (128 * GB_STRIDE)   // 10240
#define GB_BUF    (4 * GB_TILE)       // 40960
#define GB_NBUF   3
#define GB_SMEM   (GB_NBUF * GB_BUF)  // 122880
#define SCALE_A 256.0f
#define SCALE_W 4096.0f
#define INV_SCALE (1.0f / (256.0f * 4096.0f))

__device__ __forceinline__ uint32_t smem_u32(const void* p) {
    uint32_t a;
    asm("{ .reg .u64 t; cvta.to.shared.u64 t, %1; cvt.u32.u64 %0, t; }" : "=r"(a) : "l"(p));
    return a;
}
__device__ __forceinline__ void ldsm_x4(uint32_t& r0, uint32_t& r1, uint32_t& r2,
                                        uint32_t& r3, uint32_t addr) {
    asm volatile("ldmatrix.sync.aligned.m8n8.x4.shared.b16 {%0,%1,%2,%3}, [%4];"
                 : "=r"(r0), "=r"(r1), "=r"(r2), "=r"(r3) : "r"(addr));
}
__device__ __forceinline__ void mma_f16(float* d, const uint32_t* a, const uint32_t* b) {
    asm volatile("mma.sync.aligned.m16n8k16.row.col.f32.f16.f16.f32 "
                 "{%0,%1,%2,%3}, {%4,%5,%6,%7}, {%8,%9}, {%0,%1,%2,%3};"
                 : "+f"(d[0]), "+f"(d[1]), "+f"(d[2]), "+f"(d[3])
                 : "r"(a[0]), "r"(a[1]), "r"(a[2]), "r"(a[3]), "r"(b[0]), "r"(b[1]));
}
__device__ __forceinline__ void split4h(float4 v, float sc,
                                        uint32_t& h0, uint32_t& h1,
                                        uint32_t& l0, uint32_t& l1) {
    float x = v.x * sc, y = v.y * sc, z = v.z * sc, w = v.w * sc;
    __half2 a01 = __floats2half2_rn(x, y);
    __half2 a23 = __floats2half2_rn(z, w);
    float2 f01 = __half22float2(a01);
    float2 f23 = __half22float2(a23);
    __half2 r01 = __floats2half2_rn(x - f01.x, y - f01.y);
    __half2 r23 = __floats2half2_rn(z - f23.x, w - f23.y);
    h0 = *reinterpret_cast<uint32_t*>(&a01);
    h1 = *reinterpret_cast<uint32_t*>(&a23);
    l0 = *reinterpret_cast<uint32_t*>(&r01);
    l1 = *reinterpret_cast<uint32_t*>(&r23);
}

struct GbRegs { float4 Ar[4]; float4 Wr[4]; };

__device__ __forceinline__ void gb_ldg(GbRegs& R, const float* aB, const float* wB, size_t kf) {
#pragma unroll
    for (int i = 0; i < 4; i++) {
        R.Ar[i] = *reinterpret_cast<const float4*>(aB + (size_t)(32 * i) * S2 + kf);
        R.Wr[i] = *reinterpret_cast<const float4*>(wB + (size_t)(32 * i) * S2 + kf);
    }
}
__device__ __forceinline__ void gb_sts(const GbRegs& R, char* buf, int lrow, int lg) {
#pragma unroll
    for (int i = 0; i < 4; i++) {
        uint32_t h0, h1, l0, l1;
        uint32_t off = (uint32_t)(lrow + 32 * i) * GB_STRIDE + lg * 8;
        split4h(R.Ar[i], SCALE_A, h0, h1, l0, l1);
        *reinterpret_cast<uint2*>(buf + 0 * GB_TILE + off) = make_uint2(h0, h1);
        *reinterpret_cast<uint2*>(buf + 1 * GB_TILE + off) = make_uint2(l0, l1);
        split4h(R.Wr[i], SCALE_W, h0, h1, l0, l1);
        *reinterpret_cast<uint2*>(buf + 2 * GB_TILE + off) = make_uint2(h0, h1);
        *reinterpret_cast<uint2*>(buf + 3 * GB_TILE + off) = make_uint2(l0, l1);
    }
}

__global__ __launch_bounds__(256, 1) void big_gemm_hmma(
    const float* __restrict__ A,
    const float* __restrict__ Wc1, const float* __restrict__ W1)
{
    extern __shared__ char smem[];
    const uint32_t sbase = smem_u32(smem);
    const int tid = threadIdx.x;
    const int lane = tid & 31, wid = tid >> 5;
    const int wm = wid & 3, wn = wid >> 2;

    // job decode: 24 tiles x 6 split-K  (identical to round-4)
    int b = blockIdx.x;
    int t = b / 6, z = b % 6;
    const float* W; float* C; int N, mt, nt;
    if (t < 8) { W = Wc1; C = g_cxpre; N = HID;     mt = t & 1; nt = t >> 1; }
    else { t -= 8; W = W1; C = g_x1;   N = 2 * HID; mt = t & 1; nt = t >> 1; }
    const int mbase = mt * 128, nbase = nt * 128;
    const int c0 = z * 1024 / 6, c1 = (z + 1) * 1024 / 6;
    const int n = c1 - c0;

    const int lrow = tid >> 3;
    const int lg   = tid & 7;
    const float* aB = A + (size_t)(mbase + lrow) * S2 + lg * 4;
    const float* wB = W + (size_t)(nbase + lrow) * S2 + lg * 4;

    float acc[2][8][4];
#pragma unroll
    for (int i = 0; i < 2; i++)
#pragma unroll
        for (int j = 0; j < 8; j++)
#pragma unroll
            for (int r = 0; r < 4; r++) acc[i][j][r] = 0.f;

    // MMA operand addresses per buffer are buffer-relative constants
    const uint32_t a_rel = (uint32_t)(wm * 32 + (lane & 15)) * GB_STRIDE + (lane >> 4) * 16;
    const uint32_t b_rel = 2 * GB_TILE
                         + (uint32_t)(wn * 64 + (lane & 7) + ((lane >> 4) << 3)) * GB_STRIDE
                         + ((lane >> 3) & 1) * 16;

    GbRegs R;
    // ---- prologue: stage chunk 0, prefetch chunk 1
    gb_ldg(R, aB, wB, (size_t)c0 * 32);
    gb_sts(R, smem + 0 * GB_BUF, lrow, lg);
    if (n > 1) gb_ldg(R, aB, wB, (size_t)(c0 + 1) * 32);
    __syncthreads();

    for (int li = 0; li < n; li++) {
        // stage chunk li+1 into buf[(li+1)%3]; prefetch chunk li+2
        if (li + 1 < n) {
            gb_sts(R, smem + ((li + 1) % GB_NBUF) * GB_BUF, lrow, lg);
            if (li + 2 < n) gb_ldg(R, aB, wB, (size_t)(c0 + li + 2) * 32);
        }
        __syncthreads();

        // MMA on buf[li%3] — overlaps next iteration's STS from faster warps
        const uint32_t bufb = sbase + (li % GB_NBUF) * GB_BUF;
        const uint32_t a_base = bufb + a_rel;
        const uint32_t b_base = bufb + b_rel;
#pragma unroll
        for (int ks = 0; ks < 2; ks++) {
            uint32_t af[2][2][4];
            uint32_t bf[2][8][2];
#pragma unroll
            for (int s = 0; s < 2; s++)
#pragma unroll
                for (int mi = 0; mi < 2; mi++)
                    ldsm_x4(af[s][mi][0], af[s][mi][1], af[s][mi][2], af[s][mi][3],
                            a_base + s * GB_TILE + mi * (16 * GB_STRIDE) + ks * 32);
#pragma unroll
            for (int s = 0; s < 2; s++)
#pragma unroll
                for (int nj2 = 0; nj2 < 4; nj2++) {
                    uint32_t r0, r1, r2, r3;
                    ldsm_x4(r0, r1, r2, r3,
                            b_base + s * GB_TILE + nj2 * (16 * GB_STRIDE) + ks * 32);
                    bf[s][nj2 * 2][0] = r0; bf[s][nj2 * 2][1] = r1;
                    bf[s][nj2 * 2 + 1][0] = r2; bf[s][nj2 * 2 + 1][1] = r3;
                }
#pragma unroll
            for (int mi = 0; mi < 2; mi++)
#pragma unroll
                for (int nj = 0; nj < 8; nj++) {
                    mma_f16(acc[mi][nj], af[0][mi], bf[0][nj]);   // hi*hi
                    mma_f16(acc[mi][nj], af[0][mi], bf[1][nj]);   // hi*lo
                    mma_f16(acc[mi][nj], af[1][mi], bf[0][nj]);   // lo*hi
                }
        }
    }

    // epilogue: identical to round-4
#pragma unroll
    for (int mi = 0; mi < 2; mi++) {
        int row0 = mbase + wm * 32 + mi * 16 + (lane >> 2);
#pragma unroll
        for (int nj = 0; nj < 8; nj++) {
            int col = nbase + wn * 64 + nj * 8 + (lane & 3) * 2;
            float* Cp = C + (size_t)row0 * N + col;
            atomicAdd(Cp,             acc[mi][nj][0] * INV_SCALE);
            atomicAdd(Cp + 1,         acc[mi][nj][1] * INV_SCALE);
            atomicAdd(Cp + 8 * N,     acc[mi][nj][2] * INV_SCALE);
            atomicAdd(Cp + 8 * N + 1, acc[mi][nj][3] * INV_SCALE);
        }
    }
}

// ---------------- context gate ----------------
__global__ void cx_kernel(const float* __restrict__ Wc2) {
    int row = blockIdx.x;
    int tid = threadIdx.x;
    float s = 0.f;
    for (int j = tid; j < HID; j += 128)
        s += tanhf(g_cxpre[row * HID + j]) * Wc2[j];
#pragma unroll
    for (int off = 16; off; off >>= 1) s += __shfl_xor_sync(0xffffffffu, s, off);
    __shared__ float red[4];
    if ((tid & 31) == 0) red[tid >> 5] = s;
    __syncthreads();
    if (tid == 0) {
        float t = red[0] + red[1] + red[2] + red[3];
        g_cx[row] = 1.0f / (1.0f + expf(-t));
    }
}

// ---------------- kWTA ----------------
template <int NWID>
__global__ void kwta_kernel(float* __restrict__ x) {
    __shared__ float s[NWID];
    __shared__ int cnt_gt, cnt_eq;
    const int row = blockIdx.x;
    const int tid = threadIdx.x;
    float* xr = x + (size_t)row * NWID;

    for (int i = tid; i < NWID; i += 256) s[i] = xr[i];
    if (tid == 0) { cnt_gt = 0; cnt_eq = 0; }
    int k = (int)(g_cx[row] * (float)NWID);
    __syncthreads();

    if (k <= 0) {
        for (int i = tid; i < NWID; i += 256) xr[i] = 0.f;
        return;
    }
    if (k >= NWID) return;

    for (int size = 2; size <= NWID; size <<= 1) {
        for (int stride = size >> 1; stride > 0; stride >>= 1) {
            for (int i = tid; i < NWID / 2; i += 256) {
                int idx = ((i / stride) * stride) * 2 + (i % stride);
                int partner = idx + stride;
                bool up = (idx & size) != 0;
                float a = s[idx], b2 = s[partner];
                if ((a < b2) != up) { s[idx] = b2; s[partner] = a; }
            }
            __syncthreads();
        }
    }
    float T = s[k - 1];

    int lg_ = 0, le_ = 0;
    for (int i = tid; i < NWID; i += 256) {
        float v = xr[i];
        if (v > T) lg_++;
        else if (v == T) le_++;
    }
    atomicAdd(&cnt_gt, lg_);
    atomicAdd(&cnt_eq, le_);
    __syncthreads();
    int r = k - cnt_gt;

    for (int i = tid; i < NWID; i += 256)
        if (xr[i] < T) xr[i] = 0.f;
    __syncthreads();

    if (cnt_eq != r) {
        if (tid == 0) {
            int rr = r;
            for (int i = 0; i < NWID; i++) {
                if (xr[i] == T) {
                    if (rr > 0) rr--;
                    else xr[i] = 0.f;
                }
            }
        }
    }
}

// ---------------- launch ----------------
extern "C" void kernel_launch(void* const* d_in, const int* in_sizes, int n_in,
                              void* d_out, int out_size) {
    const float* input = (const float*)d_in[0];
    const float* W_c1  = (const float*)d_in[1];
    const float* b_c1  = (const float*)d_in[2];
    const float* W_c2  = (const float*)d_in[3];
    const float* W1    = (const float*)d_in[4];
    const float* b1    = (const float*)d_in[5];
    const float* W2    = (const float*)d_in[6];
    const float* b2    = (const float*)d_in[7];
    const float* W3    = (const float*)d_in[8];
    const float* b3    = (const float*)d_in[9];
    const float* W4    = (const float*)d_in[10];
    float* out = (float*)d_out;

    float *cxpre, *x1, *x2, *x3;
    cudaGetSymbolAddress((void**)&cxpre, g_cxpre);
    cudaGetSymbolAddress((void**)&x1, g_x1);
    cudaGetSymbolAddress((void**)&x2, g_x2);
    cudaGetSymbolAddress((void**)&x3, g_x3);

    cudaFuncSetAttribute(big_gemm_hmma, cudaFuncAttributeMaxDynamicSharedMemorySize, GB_SMEM);

    bias_init_kernel<<<(BATCH * HID + 255) / 256, 256>>>(cxpre, b_c1, BATCH * HID, HID);
    bias_init_kernel<<<(BATCH * 2 * HID + 255) / 256, 256>>>(x1, b1, BATCH * 2 * HID, 2 * HID);
    bias_init_kernel<<<(BATCH * HEADS + 255) / 256, 256>>>(out, nullptr, BATCH * HEADS, HEADS);

    big_gemm_hmma<<<144, 256, GB_SMEM>>>(input, W_c1, W1);

    cx_kernel<<<BATCH, 128>>>(W_c2);
    kwta_kernel<2 * HID><<<BATCH, 256>>>(x1);

    bias_init_kernel<<<(BATCH * HID + 255) / 256, 256>>>(x2, b2, BATCH * HID, HID);
    {
        dim3 g(HID / BN, BATCH / BM, 4);
        splitk_gemm<<<g, 256>>>(x1, W2, x2, BATCH, HID, 2 * HID, (2 * HID) / 4);
    }
    kwta_kernel<HID><<<BATCH, 256>>>(x2);

    bias_init_kernel<<<(BATCH * HEADS + 255) / 256, 256>>>(x3, b3, BATCH * HEADS, HEADS);
    {
        dim3 g(HEADS / BN, BATCH / BM, 2);
        splitk_gemm<<<g, 256>>>(x2, W3, x3, BATCH, HEADS, HID, HID / 2);
    }
    kwta_kernel<HEADS><<<BATCH, 256>>>(x3);

    {
        dim3 g(HEADS / BN, BATCH / BM, 4);
        splitk_gemm<<<g, 256>>>(x3, W4, out, BATCH, HEADS, HEADS, HEADS / 4);
    }
}

// round 6
// speedup vs baseline: 3.1440x; 1.0155x over previous
#include <cuda_runtime.h>
#include <cuda_fp16.h>
#include <cstdint>

#define BATCH 256
#define S2    32768
#define HID   512
#define HEADS 1024

// ---------------- scratch ----------------
__device__ float g_cxpre[BATCH * HID];
__device__ float g_cx[BATCH];
__device__ float g_x1[BATCH * 2 * HID];
__device__ float g_x2[BATCH * HID];
__device__ float g_x3[BATCH * HEADS];

// ---------------- fused init: all biases / zeros in one launch ----------------
__global__ void init_all_kernel(const float* __restrict__ b_c1, const float* __restrict__ b1,
                                const float* __restrict__ b2, const float* __restrict__ b3,
                                float* __restrict__ out) {
    int i = blockIdx.x * 256 + threadIdx.x;
    if (i < 131072) {                       // g_cxpre [256,512]
        g_cxpre[i] = b_c1[i & 511];
    } else if (i < 393216) {                // g_x1 [256,1024]
        int j = i - 131072; g_x1[j] = b1[j & 1023];
    } else if (i < 655360) {                // out [256,1024] zero
        out[i - 393216] = 0.0f;
    } else if (i < 786432) {                // g_x2 [256,512]
        int j = i - 655360; g_x2[j] = b2[j & 511];
    } else {                                // g_x3 [256,1024]
        int j = i - 786432; g_x3[j] = b3[j & 1023];
    }
}

// ---------------- fp32 split-K GEMM (small layers; numerics frozen) ----------------
#define BM 64
#define BN 64
#define BKK 32
#define AS_STRIDE 33
#define WS_STRIDE 68

__global__ __launch_bounds__(256) void splitk_gemm(
    const float* __restrict__ A, const float* __restrict__ W,
    float* __restrict__ C, int M, int N, int K, int kchunk)
{
    __shared__ float As[BM * AS_STRIDE];
    __shared__ float Ws[BKK * WS_STRIDE];

    const int tid  = threadIdx.x;
    const int mbase = blockIdx.y * BM;
    const int nbase = blockIdx.x * BN;
    const int k0    = blockIdx.z * kchunk;

    const int lane = tid & 31, warp = tid >> 5;
    const int wm = warp & 3, wn = warp >> 2;
    const int m0 = wm * 16 + (lane >> 3) * 4;
    const int n0 = wn * 32 + (lane & 7) * 4;

    unsigned long long acc[4][2];
#pragma unroll
    for (int i = 0; i < 4; i++) { acc[i][0] = 0ull; acc[i][1] = 0ull; }

    for (int kk = k0; kk < k0 + kchunk; kk += BKK) {
#pragma unroll
        for (int l = 0; l < 2; l++) {
            int f   = tid + l * 256;
            int row = f >> 3;
            int kc  = (f & 7) * 4;
            float4 va = *reinterpret_cast<const float4*>(&A[(size_t)(mbase + row) * K + kk + kc]);
            As[row * AS_STRIDE + kc + 0] = va.x;
            As[row * AS_STRIDE + kc + 1] = va.y;
            As[row * AS_STRIDE + kc + 2] = va.z;
            As[row * AS_STRIDE + kc + 3] = va.w;
            float4 vw = *reinterpret_cast<const float4*>(&W[(size_t)(nbase + row) * K + kk + kc]);
            Ws[(kc + 0) * WS_STRIDE + row] = vw.x;
            Ws[(kc + 1) * WS_STRIDE + row] = vw.y;
            Ws[(kc + 2) * WS_STRIDE + row] = vw.z;
            Ws[(kc + 3) * WS_STRIDE + row] = vw.w;
        }
        __syncthreads();

#pragma unroll
        for (int k = 0; k < BKK; k++) {
            unsigned long long pa[4];
#pragma unroll
            for (int i = 0; i < 4; i++) {
                unsigned int au = __float_as_uint(As[(m0 + i) * AS_STRIDE + k]);
                asm("mov.b64 %0, {%1, %1};" : "=l"(pa[i]) : "r"(au));
            }
            unsigned long long w0 = *reinterpret_cast<const unsigned long long*>(&Ws[k * WS_STRIDE + n0]);
            unsigned long long w1 = *reinterpret_cast<const unsigned long long*>(&Ws[k * WS_STRIDE + n0 + 2]);
#pragma unroll
            for (int i = 0; i < 4; i++) {
                asm("fma.rn.f32x2 %0, %1, %2, %0;" : "+l"(acc[i][0]) : "l"(pa[i]), "l"(w0));
                asm("fma.rn.f32x2 %0, %1, %2, %0;" : "+l"(acc[i][1]) : "l"(pa[i]), "l"(w1));
            }
        }
        __syncthreads();
    }

#pragma unroll
    for (int i = 0; i < 4; i++) {
#pragma unroll
        for (int j = 0; j < 2; j++) {
            float lo = __uint_as_float((unsigned)(acc[i][j] & 0xffffffffull));
            float hi = __uint_as_float((unsigned)(acc[i][j] >> 32));
            size_t base = (size_t)(mbase + m0 + i) * N + nbase + n0 + 2 * j;
            atomicAdd(&C[base], lo);
            atomicAdd(&C[base + 1], hi);
        }
    }
}

// ============================================================================
// Big GEMMs via mma.sync fp16 hi/lo 3-product. NUMERICS BITWISE FROZEN vs
// round-5: identical tile values, per-warp MMA order, split-K partition and
// epilogue adds. Reorganized: 128-thread (4-warp) CTAs, tile 128x64, 288 CTAs
// -> 2 CTAs/SM so tensor work of one CTA hides barrier/LDSM stalls of the other.
// ============================================================================
#define GB_STRIDE 80
#define A_TILE   (128 * GB_STRIDE)    // 10240
#define W_TILE   (64 * GB_STRIDE)     // 5120
#define GB_BUF   (2 * A_TILE + 2 * W_TILE)  // 30720
#define GB_NBUF  3
#define GB_SMEM  (GB_NBUF * GB_BUF)   // 92160
#define SCALE_A 256.0f
#define SCALE_W 4096.0f
#define INV_SCALE (1.0f / (256.0f * 4096.0f))

__device__ __forceinline__ uint32_t smem_u32(const void* p) {
    uint32_t a;
    asm("{ .reg .u64 t; cvta.to.shared.u64 t, %1; cvt.u32.u64 %0, t; }" : "=r"(a) : "l"(p));
    return a;
}
__device__ __forceinline__ void ldsm_x4(uint32_t& r0, uint32_t& r1, uint32_t& r2,
                                        uint32_t& r3, uint32_t addr) {
    asm volatile("ldmatrix.sync.aligned.m8n8.x4.shared.b16 {%0,%1,%2,%3}, [%4];"
                 : "=r"(r0), "=r"(r1), "=r"(r2), "=r"(r3) : "r"(addr));
}
__device__ __forceinline__ void mma_f16(float* d, const uint32_t* a, const uint32_t* b) {
    asm volatile("mma.sync.aligned.m16n8k16.row.col.f32.f16.f16.f32 "
                 "{%0,%1,%2,%3}, {%4,%5,%6,%7}, {%8,%9}, {%0,%1,%2,%3};"
                 : "+f"(d[0]), "+f"(d[1]), "+f"(d[2]), "+f"(d[3])
                 : "r"(a[0]), "r"(a[1]), "r"(a[2]), "r"(a[3]), "r"(b[0]), "r"(b[1]));
}
__device__ __forceinline__ void split4h(float4 v, float sc,
                                        uint32_t& h0, uint32_t& h1,
                                        uint32_t& l0, uint32_t& l1) {
    float x = v.x * sc, y = v.y * sc, z = v.z * sc, w = v.w * sc;
    __half2 a01 = __floats2half2_rn(x, y);
    __half2 a23 = __floats2half2_rn(z, w);
    float2 f01 = __half22float2(a01);
    float2 f23 = __half22float2(a23);
    __half2 r01 = __floats2half2_rn(x - f01.x, y - f01.y);
    __half2 r23 = __floats2half2_rn(z - f23.x, w - f23.y);
    h0 = *reinterpret_cast<uint32_t*>(&a01);
    h1 = *reinterpret_cast<uint32_t*>(&a23);
    l0 = *reinterpret_cast<uint32_t*>(&r01);
    l1 = *reinterpret_cast<uint32_t*>(&r23);
}

struct GbRegs { float4 Ar[8]; float4 Wr[4]; };

__device__ __forceinline__ void gb_ldg(GbRegs& R, const float* aB, const float* wB, size_t kf) {
#pragma unroll
    for (int i = 0; i < 8; i++)
        R.Ar[i] = *reinterpret_cast<const float4*>(aB + (size_t)(16 * i) * S2 + kf);
#pragma unroll
    for (int i = 0; i < 4; i++)
        R.Wr[i] = *reinterpret_cast<const float4*>(wB + (size_t)(16 * i) * S2 + kf);
}
__device__ __forceinline__ void gb_sts(const GbRegs& R, char* buf, int lrow, int lg) {
#pragma unroll
    for (int i = 0; i < 8; i++) {
        uint32_t h0, h1, l0, l1;
        uint32_t off = (uint32_t)(lrow + 16 * i) * GB_STRIDE + lg * 8;
        split4h(R.Ar[i], SCALE_A, h0, h1, l0, l1);
        *reinterpret_cast<uint2*>(buf + off) = make_uint2(h0, h1);
        *reinterpret_cast<uint2*>(buf + A_TILE + off) = make_uint2(l0, l1);
    }
#pragma unroll
    for (int i = 0; i < 4; i++) {
        uint32_t h0, h1, l0, l1;
        uint32_t off = (uint32_t)(lrow + 16 * i) * GB_STRIDE + lg * 8;
        split4h(R.Wr[i], SCALE_W, h0, h1, l0, l1);
        *reinterpret_cast<uint2*>(buf + 2 * A_TILE + off) = make_uint2(h0, h1);
        *reinterpret_cast<uint2*>(buf + 2 * A_TILE + W_TILE + off) = make_uint2(l0, l1);
    }
}

__global__ __launch_bounds__(128, 2) void big_gemm_hmma(
    const float* __restrict__ A,
    const float* __restrict__ Wc1, const float* __restrict__ W1)
{
    extern __shared__ char smem[];
    const uint32_t sbase = smem_u32(smem);
    const int tid = threadIdx.x;
    const int lane = tid & 31, wm = tid >> 5;   // 4 warps: wm = m-position

    // job decode: 48 tiles (128x64) x 6 split-K = 288 CTAs
    int b = blockIdx.x;
    int t = b / 6, z = b % 6;
    const float* W; float* C; int N, mt, nt;
    if (t < 16) { W = Wc1; C = g_cxpre; N = HID;     mt = t & 1; nt = t >> 1; }  // 8 n-tiles
    else { t -= 16; W = W1; C = g_x1;   N = 2 * HID; mt = t & 1; nt = t >> 1; }  // 16 n-tiles
    const int mbase = mt * 128, nbase = nt * 64;
    const int c0 = z * 1024 / 6, c1 = (z + 1) * 1024 / 6;
    const int n = c1 - c0;

    const int lrow = tid >> 3;     // 0..15
    const int lg   = tid & 7;
    const float* aB = A + (size_t)(mbase + lrow) * S2 + lg * 4;
    const float* wB = W + (size_t)(nbase + lrow) * S2 + lg * 4;

    float acc[2][8][4];
#pragma unroll
    for (int i = 0; i < 2; i++)
#pragma unroll
        for (int j = 0; j < 8; j++)
#pragma unroll
            for (int r = 0; r < 4; r++) acc[i][j][r] = 0.f;

    const uint32_t a_rel = (uint32_t)(wm * 32 + (lane & 15)) * GB_STRIDE + (lane >> 4) * 16;
    const uint32_t b_rel = 2 * A_TILE
                         + (uint32_t)((lane & 7) + ((lane >> 4) << 3)) * GB_STRIDE
                         + ((lane >> 3) & 1) * 16;

    GbRegs R;
    gb_ldg(R, aB, wB, (size_t)c0 * 32);
    gb_sts(R, smem + 0 * GB_BUF, lrow, lg);
    if (n > 1) gb_ldg(R, aB, wB, (size_t)(c0 + 1) * 32);
    __syncthreads();

    for (int li = 0; li < n; li++) {
        if (li + 1 < n) {
            gb_sts(R, smem + ((li + 1) % GB_NBUF) * GB_BUF, lrow, lg);
            if (li + 2 < n) gb_ldg(R, aB, wB, (size_t)(c0 + li + 2) * 32);
        }
        __syncthreads();

        const uint32_t bufb = sbase + (li % GB_NBUF) * GB_BUF;
        const uint32_t a_base = bufb + a_rel;
        const uint32_t b_base = bufb + b_rel;
#pragma unroll
        for (int ks = 0; ks < 2; ks++) {
            uint32_t af[2][2][4];
            uint32_t bf[2][8][2];
#pragma unroll
            for (int s = 0; s < 2; s++)
#pragma unroll
                for (int mi = 0; mi < 2; mi++)
                    ldsm_x4(af[s][mi][0], af[s][mi][1], af[s][mi][2], af[s][mi][3],
                            a_base + s * A_TILE + mi * (16 * GB_STRIDE) + ks * 32);
#pragma unroll
            for (int s = 0; s < 2; s++)
#pragma unroll
                for (int nj2 = 0; nj2 < 4; nj2++) {
                    uint32_t r0, r1, r2, r3;
                    ldsm_x4(r0, r1, r2, r3,
                            b_base + s * W_TILE + nj2 * (16 * GB_STRIDE) + ks * 32);
                    bf[s][nj2 * 2][0] = r0; bf[s][nj2 * 2][1] = r1;
                    bf[s][nj2 * 2 + 1][0] = r2; bf[s][nj2 * 2 + 1][1] = r3;
                }
#pragma unroll
            for (int mi = 0; mi < 2; mi++)
#pragma unroll
                for (int nj = 0; nj < 8; nj++) {
                    mma_f16(acc[mi][nj], af[0][mi], bf[0][nj]);   // hi*hi
                    mma_f16(acc[mi][nj], af[0][mi], bf[1][nj]);   // hi*lo
                    mma_f16(acc[mi][nj], af[1][mi], bf[0][nj]);   // lo*hi
                }
        }
    }

    // epilogue: identical adds into bias-preinit C
#pragma unroll
    for (int mi = 0; mi < 2; mi++) {
        int row0 = mbase + wm * 32 + mi * 16 + (lane >> 2);
#pragma unroll
        for (int nj = 0; nj < 8; nj++) {
            int col = nbase + nj * 8 + (lane & 3) * 2;
            float* Cp = C + (size_t)row0 * N + col;
            atomicAdd(Cp,             acc[mi][nj][0] * INV_SCALE);
            atomicAdd(Cp + 1,         acc[mi][nj][1] * INV_SCALE);
            atomicAdd(Cp + 8 * N,     acc[mi][nj][2] * INV_SCALE);
            atomicAdd(Cp + 8 * N + 1, acc[mi][nj][3] * INV_SCALE);
        }
    }
}

// ---------------- context gate ----------------
__global__ void cx_kernel(const float* __restrict__ Wc2) {
    int row = blockIdx.x;
    int tid = threadIdx.x;
    float s = 0.f;
    for (int j = tid; j < HID; j += 128)
        s += tanhf(g_cxpre[row * HID + j]) * Wc2[j];
#pragma unroll
    for (int off = 16; off; off >>= 1) s += __shfl_xor_sync(0xffffffffu, s, off);
    __shared__ float red[4];
    if ((tid & 31) == 0) red[tid >> 5] = s;
    __syncthreads();
    if (tid == 0) {
        float t = red[0] + red[1] + red[2] + red[3];
        g_cx[row] = 1.0f / (1.0f + expf(-t));
    }
}

// ---------------- kWTA (512 threads; identical bitonic network) ----------------
template <int NWID>
__global__ void kwta_kernel(float* __restrict__ x) {
    __shared__ float s[NWID];
    __shared__ int cnt_gt, cnt_eq;
    const int row = blockIdx.x;
    const int tid = threadIdx.x;  // 512
    float* xr = x + (size_t)row * NWID;

    for (int i = tid; i < NWID; i += 512) s[i] = xr[i];
    if (tid == 0) { cnt_gt = 0; cnt_eq = 0; }
    int k = (int)(g_cx[row] * (float)NWID);
    __syncthreads();

    if (k <= 0) {
        for (int i = tid; i < NWID; i += 512) xr[i] = 0.f;
        return;
    }
    if (k >= NWID) return;

    for (int size = 2; size <= NWID; size <<= 1) {
        for (int stride = size >> 1; stride > 0; stride >>= 1) {
            for (int i = tid; i < NWID / 2; i += 512) {
                int idx = ((i / stride) * stride) * 2 + (i % stride);
                int partner = idx + stride;
                bool up = (idx & size) != 0;
                float a = s[idx], b2 = s[partner];
                if ((a < b2) != up) { s[idx] = b2; s[partner] = a; }
            }
            __syncthreads();
        }
    }
    float T = s[k - 1];

    int lg_ = 0, le_ = 0;
    for (int i = tid; i < NWID; i += 512) {
        float v = xr[i];
        if (v > T) lg_++;
        else if (v == T) le_++;
    }
    atomicAdd(&cnt_gt, lg_);
    atomicAdd(&cnt_eq, le_);
    __syncthreads();
    int r = k - cnt_gt;

    for (int i = tid; i < NWID; i += 512)
        if (xr[i] < T) xr[i] = 0.f;
    __syncthreads();

    if (cnt_eq != r) {
        if (tid == 0) {
            int rr = r;
            for (int i = 0; i < NWID; i++) {
                if (xr[i] == T) {
                    if (rr > 0) rr--;
                    else xr[i] = 0.f;
                }
            }
        }
    }
}

// ---------------- launch ----------------
extern "C" void kernel_launch(void* const* d_in, const int* in_sizes, int n_in,
                              void* d_out, int out_size) {
    const float* input = (const float*)d_in[0];
    const float* W_c1  = (const float*)d_in[1];
    const float* b_c1  = (const float*)d_in[2];
    const float* W_c2  = (const float*)d_in[3];
    const float* W1    = (const float*)d_in[4];
    const float* b1    = (const float*)d_in[5];
    const float* W2    = (const float*)d_in[6];
    const float* b2    = (const float*)d_in[7];
    const float* W3    = (const float*)d_in[8];
    const float* b3    = (const float*)d_in[9];
    const float* W4    = (const float*)d_in[10];
    float* out = (float*)d_out;

    float *x1, *x2, *x3;
    cudaGetSymbolAddress((void**)&x1, g_x1);
    cudaGetSymbolAddress((void**)&x2, g_x2);
    cudaGetSymbolAddress((void**)&x3, g_x3);

    cudaFuncSetAttribute(big_gemm_hmma, cudaFuncAttributeMaxDynamicSharedMemorySize, GB_SMEM);

    // all accumulator inits (biases/zeros) in one launch
    init_all_kernel<<<4096, 256>>>(b_c1, b1, b2, b3, out);

    // both big GEMMs: 288 CTAs, 2 per SM
    big_gemm_hmma<<<288, 128, GB_SMEM>>>(input, W_c1, W1);

    cx_kernel<<<BATCH, 128>>>(W_c2);
    kwta_kernel<2 * HID><<<BATCH, 512>>>(x1);

    {
        dim3 g(HID / BN, BATCH / BM, 4);
        splitk_gemm<<<g, 256>>>(x1, W2, x2, BATCH, HID, 2 * HID, (2 * HID) / 4);
    }
    kwta_kernel<HID><<<BATCH, 512>>>(x2);

    {
        dim3 g(HEADS / BN, BATCH / BM, 2);
        splitk_gemm<<<g, 256>>>(x2, W3, x3, BATCH, HEADS, HID, HID / 2);
    }
    kwta_kernel<HEADS><<<BATCH, 512>>>(x3);

    {
        dim3 g(HEADS / BN, BATCH / BM, 4);
        splitk_gemm<<<g, 256>>>(x3, W4, out, BATCH, HEADS, HEADS, HEADS / 4);
    }
}

// round 7
// speedup vs baseline: 3.2499x; 1.0337x over previous
#include <cuda_runtime.h>
#include <cuda_fp16.h>
#include <cstdint>

#define BATCH 256
#define S2    32768
#define HID   512
#define HEADS 1024

// ---------------- scratch ----------------
__device__ float g_cxpre[BATCH * HID];
__device__ float g_cx[BATCH];
__device__ float g_x1[BATCH * 2 * HID];
__device__ float g_x2[BATCH * HID];
__device__ float g_x3[BATCH * HEADS];

// ---------------- fused init ----------------
__global__ void init_all_kernel(const float* __restrict__ b_c1, const float* __restrict__ b1,
                                const float* __restrict__ b2, const float* __restrict__ b3,
                                float* __restrict__ out) {
    int i = blockIdx.x * 256 + threadIdx.x;
    if (i < 131072) {
        g_cxpre[i] = b_c1[i & 511];
    } else if (i < 393216) {
        int j = i - 131072; g_x1[j] = b1[j & 1023];
    } else if (i < 655360) {
        out[i - 393216] = 0.0f;
    } else if (i < 786432) {
        int j = i - 655360; g_x2[j] = b2[j & 511];
    } else {
        int j = i - 786432; g_x3[j] = b3[j & 1023];
    }
}

// ---------------- fp32 split-K GEMM (small layers; numerics frozen) ----------------
#define BM 64
#define BN 64
#define BKK 32
#define AS_STRIDE 33
#define WS_STRIDE 68

__global__ __launch_bounds__(256) void splitk_gemm(
    const float* __restrict__ A, const float* __restrict__ W,
    float* __restrict__ C, int M, int N, int K, int kchunk)
{
    __shared__ float As[BM * AS_STRIDE];
    __shared__ float Ws[BKK * WS_STRIDE];

    const int tid  = threadIdx.x;
    const int mbase = blockIdx.y * BM;
    const int nbase = blockIdx.x * BN;
    const int k0    = blockIdx.z * kchunk;

    const int lane = tid & 31, warp = tid >> 5;
    const int wm = warp & 3, wn = warp >> 2;
    const int m0 = wm * 16 + (lane >> 3) * 4;
    const int n0 = wn * 32 + (lane & 7) * 4;

    unsigned long long acc[4][2];
#pragma unroll
    for (int i = 0; i < 4; i++) { acc[i][0] = 0ull; acc[i][1] = 0ull; }

    for (int kk = k0; kk < k0 + kchunk; kk += BKK) {
#pragma unroll
        for (int l = 0; l < 2; l++) {
            int f   = tid + l * 256;
            int row = f >> 3;
            int kc  = (f & 7) * 4;
            float4 va = *reinterpret_cast<const float4*>(&A[(size_t)(mbase + row) * K + kk + kc]);
            As[row * AS_STRIDE + kc + 0] = va.x;
            As[row * AS_STRIDE + kc + 1] = va.y;
            As[row * AS_STRIDE + kc + 2] = va.z;
            As[row * AS_STRIDE + kc + 3] = va.w;
            float4 vw = *reinterpret_cast<const float4*>(&W[(size_t)(nbase + row) * K + kk + kc]);
            Ws[(kc + 0) * WS_STRIDE + row] = vw.x;
            Ws[(kc + 1) * WS_STRIDE + row] = vw.y;
            Ws[(kc + 2) * WS_STRIDE + row] = vw.z;
            Ws[(kc + 3) * WS_STRIDE + row] = vw.w;
        }
        __syncthreads();

#pragma unroll
        for (int k = 0; k < BKK; k++) {
            unsigned long long pa[4];
#pragma unroll
            for (int i = 0; i < 4; i++) {
                unsigned int au = __float_as_uint(As[(m0 + i) * AS_STRIDE + k]);
                asm("mov.b64 %0, {%1, %1};" : "=l"(pa[i]) : "r"(au));
            }
            unsigned long long w0 = *reinterpret_cast<const unsigned long long*>(&Ws[k * WS_STRIDE + n0]);
            unsigned long long w1 = *reinterpret_cast<const unsigned long long*>(&Ws[k * WS_STRIDE + n0 + 2]);
#pragma unroll
            for (int i = 0; i < 4; i++) {
                asm("fma.rn.f32x2 %0, %1, %2, %0;" : "+l"(acc[i][0]) : "l"(pa[i]), "l"(w0));
                asm("fma.rn.f32x2 %0, %1, %2, %0;" : "+l"(acc[i][1]) : "l"(pa[i]), "l"(w1));
            }
        }
        __syncthreads();
    }

#pragma unroll
    for (int i = 0; i < 4; i++) {
#pragma unroll
        for (int j = 0; j < 2; j++) {
            float lo = __uint_as_float((unsigned)(acc[i][j] & 0xffffffffull));
            float hi = __uint_as_float((unsigned)(acc[i][j] >> 32));
            size_t base = (size_t)(mbase + m0 + i) * N + nbase + n0 + 2 * j;
            atomicAdd(&C[base], lo);
            atomicAdd(&C[base + 1], hi);
        }
    }
}

// ============================================================================
// Big GEMMs via mma.sync fp16 hi/lo 3-product. BYTE-IDENTICAL to round-6.
// ============================================================================
#define GB_STRIDE 80
#define A_TILE   (128 * GB_STRIDE)
#define W_TILE   (64 * GB_STRIDE)
#define GB_BUF   (2 * A_TILE + 2 * W_TILE)
#define GB_NBUF  3
#define GB_SMEM  (GB_NBUF * GB_BUF)
#define SCALE_A 256.0f
#define SCALE_W 4096.0f
#define INV_SCALE (1.0f / (256.0f * 4096.0f))

__device__ __forceinline__ uint32_t smem_u32(const void* p) {
    uint32_t a;
    asm("{ .reg .u64 t; cvta.to.shared.u64 t, %1; cvt.u32.u64 %0, t; }" : "=r"(a) : "l"(p));
    return a;
}
__device__ __forceinline__ void ldsm_x4(uint32_t& r0, uint32_t& r1, uint32_t& r2,
                                        uint32_t& r3, uint32_t addr) {
    asm volatile("ldmatrix.sync.aligned.m8n8.x4.shared.b16 {%0,%1,%2,%3}, [%4];"
                 : "=r"(r0), "=r"(r1), "=r"(r2), "=r"(r3) : "r"(addr));
}
__device__ __forceinline__ void mma_f16(float* d, const uint32_t* a, const uint32_t* b) {
    asm volatile("mma.sync.aligned.m16n8k16.row.col.f32.f16.f16.f32 "
                 "{%0,%1,%2,%3}, {%4,%5,%6,%7}, {%8,%9}, {%0,%1,%2,%3};"
                 : "+f"(d[0]), "+f"(d[1]), "+f"(d[2]), "+f"(d[3])
                 : "r"(a[0]), "r"(a[1]), "r"(a[2]), "r"(a[3]), "r"(b[0]), "r"(b[1]));
}
__device__ __forceinline__ void split4h(float4 v, float sc,
                                        uint32_t& h0, uint32_t& h1,
                                        uint32_t& l0, uint32_t& l1) {
    float x = v.x * sc, y = v.y * sc, z = v.z * sc, w = v.w * sc;
    __half2 a01 = __floats2half2_rn(x, y);
    __half2 a23 = __floats2half2_rn(z, w);
    float2 f01 = __half22float2(a01);
    float2 f23 = __half22float2(a23);
    __half2 r01 = __floats2half2_rn(x - f01.x, y - f01.y);
    __half2 r23 = __floats2half2_rn(z - f23.x, w - f23.y);
    h0 = *reinterpret_cast<uint32_t*>(&a01);
    h1 = *reinterpret_cast<uint32_t*>(&a23);
    l0 = *reinterpret_cast<uint32_t*>(&r01);
    l1 = *reinterpret_cast<uint32_t*>(&r23);
}

struct GbRegs { float4 Ar[8]; float4 Wr[4]; };

__device__ __forceinline__ void gb_ldg(GbRegs& R, const float* aB, const float* wB, size_t kf) {
#pragma unroll
    for (int i = 0; i < 8; i++)
        R.Ar[i] = *reinterpret_cast<const float4*>(aB + (size_t)(16 * i) * S2 + kf);
#pragma unroll
    for (int i = 0; i < 4; i++)
        R.Wr[i] = *reinterpret_cast<const float4*>(wB + (size_t)(16 * i) * S2 + kf);
}
__device__ __forceinline__ void gb_sts(const GbRegs& R, char* buf, int lrow, int lg) {
#pragma unroll
    for (int i = 0; i < 8; i++) {
        uint32_t h0, h1, l0, l1;
        uint32_t off = (uint32_t)(lrow + 16 * i) * GB_STRIDE + lg * 8;
        split4h(R.Ar[i], SCALE_A, h0, h1, l0, l1);
        *reinterpret_cast<uint2*>(buf + off) = make_uint2(h0, h1);
        *reinterpret_cast<uint2*>(buf + A_TILE + off) = make_uint2(l0, l1);
    }
#pragma unroll
    for (int i = 0; i < 4; i++) {
        uint32_t h0, h1, l0, l1;
        uint32_t off = (uint32_t)(lrow + 16 * i) * GB_STRIDE + lg * 8;
        split4h(R.Wr[i], SCALE_W, h0, h1, l0, l1);
        *reinterpret_cast<uint2*>(buf + 2 * A_TILE + off) = make_uint2(h0, h1);
        *reinterpret_cast<uint2*>(buf + 2 * A_TILE + W_TILE + off) = make_uint2(l0, l1);
    }
}

__global__ __launch_bounds__(128, 2) void big_gemm_hmma(
    const float* __restrict__ A,
    const float* __restrict__ Wc1, const float* __restrict__ W1)
{
    extern __shared__ char smem[];
    const uint32_t sbase = smem_u32(smem);
    const int tid = threadIdx.x;
    const int lane = tid & 31, wm = tid >> 5;

    int b = blockIdx.x;
    int t = b / 6, z = b % 6;
    const float* W; float* C; int N, mt, nt;
    if (t < 16) { W = Wc1; C = g_cxpre; N = HID;     mt = t & 1; nt = t >> 1; }
    else { t -= 16; W = W1; C = g_x1;   N = 2 * HID; mt = t & 1; nt = t >> 1; }
    const int mbase = mt * 128, nbase = nt * 64;
    const int c0 = z * 1024 / 6, c1 = (z + 1) * 1024 / 6;
    const int n = c1 - c0;

    const int lrow = tid >> 3;
    const int lg   = tid & 7;
    const float* aB = A + (size_t)(mbase + lrow) * S2 + lg * 4;
    const float* wB = W + (size_t)(nbase + lrow) * S2 + lg * 4;

    float acc[2][8][4];
#pragma unroll
    for (int i = 0; i < 2; i++)
#pragma unroll
        for (int j = 0; j < 8; j++)
#pragma unroll
            for (int r = 0; r < 4; r++) acc[i][j][r] = 0.f;

    const uint32_t a_rel = (uint32_t)(wm * 32 + (lane & 15)) * GB_STRIDE + (lane >> 4) * 16;
    const uint32_t b_rel = 2 * A_TILE
                         + (uint32_t)((lane & 7) + ((lane >> 4) << 3)) * GB_STRIDE
                         + ((lane >> 3) & 1) * 16;

    GbRegs R;
    gb_ldg(R, aB, wB, (size_t)c0 * 32);
    gb_sts(R, smem + 0 * GB_BUF, lrow, lg);
    if (n > 1) gb_ldg(R, aB, wB, (size_t)(c0 + 1) * 32);
    __syncthreads();

    for (int li = 0; li < n; li++) {
        if (li + 1 < n) {
            gb_sts(R, smem + ((li + 1) % GB_NBUF) * GB_BUF, lrow, lg);
            if (li + 2 < n) gb_ldg(R, aB, wB, (size_t)(c0 + li + 2) * 32);
        }
        __syncthreads();

        const uint32_t bufb = sbase + (li % GB_NBUF) * GB_BUF;
        const uint32_t a_base = bufb + a_rel;
        const uint32_t b_base = bufb + b_rel;
#pragma unroll
        for (int ks = 0; ks < 2; ks++) {
            uint32_t af[2][2][4];
            uint32_t bf[2][8][2];
#pragma unroll
            for (int s = 0; s < 2; s++)
#pragma unroll
                for (int mi = 0; mi < 2; mi++)
                    ldsm_x4(af[s][mi][0], af[s][mi][1], af[s][mi][2], af[s][mi][3],
                            a_base + s * A_TILE + mi * (16 * GB_STRIDE) + ks * 32);
#pragma unroll
            for (int s = 0; s < 2; s++)
#pragma unroll
                for (int nj2 = 0; nj2 < 4; nj2++) {
                    uint32_t r0, r1, r2, r3;
                    ldsm_x4(r0, r1, r2, r3,
                            b_base + s * W_TILE + nj2 * (16 * GB_STRIDE) + ks * 32);
                    bf[s][nj2 * 2][0] = r0; bf[s][nj2 * 2][1] = r1;
                    bf[s][nj2 * 2 + 1][0] = r2; bf[s][nj2 * 2 + 1][1] = r3;
                }
#pragma unroll
            for (int mi = 0; mi < 2; mi++)
#pragma unroll
                for (int nj = 0; nj < 8; nj++) {
                    mma_f16(acc[mi][nj], af[0][mi], bf[0][nj]);
                    mma_f16(acc[mi][nj], af[0][mi], bf[1][nj]);
                    mma_f16(acc[mi][nj], af[1][mi], bf[0][nj]);
                }
        }
    }

#pragma unroll
    for (int mi = 0; mi < 2; mi++) {
        int row0 = mbase + wm * 32 + mi * 16 + (lane >> 2);
#pragma unroll
        for (int nj = 0; nj < 8; nj++) {
            int col = nbase + nj * 8 + (lane & 3) * 2;
            float* Cp = C + (size_t)row0 * N + col;
            atomicAdd(Cp,             acc[mi][nj][0] * INV_SCALE);
            atomicAdd(Cp + 1,         acc[mi][nj][1] * INV_SCALE);
            atomicAdd(Cp + 8 * N,     acc[mi][nj][2] * INV_SCALE);
            atomicAdd(Cp + 8 * N + 1, acc[mi][nj][3] * INV_SCALE);
        }
    }
}

// ============================================================================
// kWTA via exact radix-select (value-identical threshold to full sort).
// DO_CX=1 additionally computes cx for the row first, replicating the old
// cx_kernel instruction-for-instruction on threads 0-127 (bitwise identical).
// ============================================================================
__device__ __forceinline__ uint32_t f2u(float f) {
    uint32_t b = __float_as_uint(f);
    return (b & 0x80000000u) ? ~b : (b | 0x80000000u);
}
__device__ __forceinline__ float u2f(uint32_t u) {
    uint32_t b = (u & 0x80000000u) ? (u & 0x7fffffffu) : ~u;
    return __uint_as_float(b);
}

template <int NWID, int DO_CX>
__global__ __launch_bounds__(512) void kwta_radix(float* __restrict__ x,
                                                  const float* __restrict__ Wc2) {
    __shared__ uint32_t keys[NWID];
    __shared__ int hist[256];
    __shared__ uint32_t sh_prefix;
    __shared__ int sh_want;
    __shared__ int cnt_gt, cnt_eq;
    __shared__ float red[4];

    const int row = blockIdx.x;
    const int tid = threadIdx.x;   // 512
    float* xr = x + (size_t)row * NWID;

    if (DO_CX) {
        // bitwise-identical replica of old cx_kernel (128 threads, same order)
        if (tid < 128) {
            float s = 0.f;
            for (int j = tid; j < HID; j += 128)
                s += tanhf(g_cxpre[row * HID + j]) * Wc2[j];
#pragma unroll
            for (int off = 16; off; off >>= 1) s += __shfl_xor_sync(0xffffffffu, s, off);
            if ((tid & 31) == 0) red[tid >> 5] = s;
        }
        __syncthreads();
        if (tid == 0) {
            float t = red[0] + red[1] + red[2] + red[3];
            g_cx[row] = 1.0f / (1.0f + expf(-t));
        }
        __syncthreads();
    }

    for (int i = tid; i < NWID; i += 512) keys[i] = f2u(xr[i]);
    const int k = (int)(g_cx[row] * (float)NWID);
    if (tid == 0) { sh_prefix = 0u; sh_want = k; cnt_gt = 0; cnt_eq = 0; }
    __syncthreads();

    if (k <= 0) {
        for (int i = tid; i < NWID; i += 512) xr[i] = 0.f;
        return;
    }
    if (k >= NWID) return;

    // 4-pass radix select (MSB first) for the k-th largest key
#pragma unroll
    for (int pass = 0; pass < 4; pass++) {
        const int shift = 24 - 8 * pass;
        if (tid < 256) hist[tid] = 0;
        __syncthreads();
        const uint32_t pref = sh_prefix;
        const int want = sh_want;
        const uint32_t maskhi = (pass == 0) ? 0u : (0xffffffffu << (shift + 8));
        for (int i = tid; i < NWID; i += 512) {
            uint32_t key = keys[i];
            if ((key & maskhi) == pref)
                atomicAdd(&hist[(key >> shift) & 255], 1);
        }
        __syncthreads();
        if (tid < 32) {
            int h[8], part = 0;
#pragma unroll
            for (int j = 0; j < 8; j++) { h[j] = hist[tid * 8 + j]; part += h[j]; }
            int suf = part;
#pragma unroll
            for (int off = 1; off < 32; off <<= 1) {
                int tt = __shfl_down_sync(0xffffffffu, suf, off);
                if (tid + off < 32) suf += tt;
            }
            int above = suf - part;     // count of keys with digit in higher lanes
            if (above < want && want <= suf) {
                int run = above;
#pragma unroll
                for (int j = 7; j >= 0; j--) {
                    run += h[j];
                    if (run >= want) {
                        sh_prefix = pref | ((uint32_t)(tid * 8 + j) << shift);
                        sh_want = want - (run - h[j]);
                        break;
                    }
                }
            }
        }
        __syncthreads();
    }

    const float T = u2f(sh_prefix);

    int lg_ = 0, le_ = 0;
    for (int i = tid; i < NWID; i += 512) {
        float v = u2f(keys[i]);
        if (v > T) lg_++;
        else if (v == T) le_++;
    }
    atomicAdd(&cnt_gt, lg_);
    atomicAdd(&cnt_eq, le_);
    __syncthreads();
    const int r = k - cnt_gt;

    for (int i = tid; i < NWID; i += 512) {
        float v = u2f(keys[i]);
        if (v < T) xr[i] = 0.f;
    }
    __syncthreads();

    if (cnt_eq != r) {      // rare tie-surplus path (stable earliest-index keep)
        if (tid == 0) {
            int rr = r;
            for (int i = 0; i < NWID; i++) {
                if (u2f(keys[i]) == T) {
                    if (rr > 0) rr--;
                    else xr[i] = 0.f;
                }
            }
        }
    }
}

// ---------------- launch ----------------
extern "C" void kernel_launch(void* const* d_in, const int* in_sizes, int n_in,
                              void* d_out, int out_size) {
    const float* input = (const float*)d_in[0];
    const float* W_c1  = (const float*)d_in[1];
    const float* b_c1  = (const float*)d_in[2];
    const float* W_c2  = (const float*)d_in[3];
    const float* W1    = (const float*)d_in[4];
    const float* b1    = (const float*)d_in[5];
    const float* W2    = (const float*)d_in[6];
    const float* b2    = (const float*)d_in[7];
    const float* W3    = (const float*)d_in[8];
    const float* b3    = (const float*)d_in[9];
    const float* W4    = (const float*)d_in[10];
    float* out = (float*)d_out;

    float *x1, *x2, *x3;
    cudaGetSymbolAddress((void**)&x1, g_x1);
    cudaGetSymbolAddress((void**)&x2, g_x2);
    cudaGetSymbolAddress((void**)&x3, g_x3);

    cudaFuncSetAttribute(big_gemm_hmma, cudaFuncAttributeMaxDynamicSharedMemorySize, GB_SMEM);

    init_all_kernel<<<4096, 256>>>(b_c1, b1, b2, b3, out);

    big_gemm_hmma<<<288, 128, GB_SMEM>>>(input, W_c1, W1);

    // cx fused into first kWTA
    kwta_radix<2 * HID, 1><<<BATCH, 512>>>(x1, W_c2);

    {
        dim3 g(HID / BN, BATCH / BM, 4);
        splitk_gemm<<<g, 256>>>(x1, W2, x2, BATCH, HID, 2 * HID, (2 * HID) / 4);
    }
    kwta_radix<HID, 0><<<BATCH, 512>>>(x2, nullptr);

    {
        dim3 g(HEADS / BN, BATCH / BM, 2);
        splitk_gemm<<<g, 256>>>(x2, W3, x3, BATCH, HEADS, HID, HID / 2);
    }
    kwta_radix<HEADS, 0><<<BATCH, 512>>>(x3, nullptr);

    {
        dim3 g(HEADS / BN, BATCH / BM, 4);
        splitk_gemm<<<g, 256>>>(x3, W4, out, BATCH, HEADS, HEADS, HEADS / 4);
    }
}